// round 13
// baseline (speedup 1.0000x reference)
#include <cuda_runtime.h>
#include <cuda_fp16.h>
#include <cstdint>
#include <math.h>

// ---------------------------------------------------------------------------
// Problem constants
// ---------------------------------------------------------------------------
#define B_   16
#define LP_  1024
#define LD_  256
#define DP_  1280
#define DE_  512
#define LC_  256

#define MPR  (B_ * LP_)      // 16384
#define MDR  (B_ * LD_)      // 4096

// ---------------------------------------------------------------------------
// Helpers
// ---------------------------------------------------------------------------
__device__ __forceinline__ uint32_t smem_u32(const void* p) {
    uint32_t a;
    asm("{ .reg .u64 t; cvta.to.shared.u64 t, %1; cvt.u32.u64 %0, t; }"
        : "=r"(a) : "l"(p));
    return a;
}

__device__ __forceinline__ void cpa16(uint32_t saddr, const void* g) {
    asm volatile("cp.async.cg.shared.global [%0], [%1], 16;"
                 :: "r"(saddr), "l"(g) : "memory");
}
#define CP_COMMIT() asm volatile("cp.async.commit_group;" ::: "memory")
#define CP_WAIT0()  asm volatile("cp.async.wait_group 0;" ::: "memory")
#define CP_WAIT1()  asm volatile("cp.async.wait_group 1;" ::: "memory")
#define CP_WAIT2()  asm volatile("cp.async.wait_group 2;" ::: "memory")

#define LDSM4(r, addr) \
    asm volatile("ldmatrix.sync.aligned.m8n8.x4.shared.b16 {%0,%1,%2,%3}, [%4];" \
        : "=r"((r)[0]), "=r"((r)[1]), "=r"((r)[2]), "=r"((r)[3]) : "r"(addr))

#define MMA16816(d, a, b) \
    asm volatile("mma.sync.aligned.m16n8k16.row.col.f32.f16.f16.f32 " \
        "{%0,%1,%2,%3}, {%4,%5,%6,%7}, {%8,%9}, {%0,%1,%2,%3};" \
        : "+f"((d)[0]), "+f"((d)[1]), "+f"((d)[2]), "+f"((d)[3]) \
        : "r"((a)[0]), "r"((a)[1]), "r"((a)[2]), "r"((a)[3]), \
          "r"((b)[0]), "r"((b)[1]))

// ---------------------------------------------------------------------------
// Scratch (fp16; hl buffers: hi at [0,sz), lo at [sz,2sz)); 16B aligned
// ---------------------------------------------------------------------------
__device__ __align__(16) __half g_prf   [(size_t)MPR * DP_];      // hi only
__device__ __align__(16) __half g_drugf [(size_t)MDR * DE_];      // hi only
__device__ __align__(16) __half g_prconf[2ull * LC_ * DP_];
__device__ __align__(16) __half g_drconf[2ull * LC_ * DE_];
__device__ __align__(16) __half g_Wqhl  [2ull * DP_ * DP_];
__device__ __align__(16) __half g_WkT   [2ull * DP_ * DP_];
__device__ __align__(16) __half g_Wq2hl [2ull * DE_ * DE_];
__device__ __align__(16) __half g_Wk2T  [2ull * DE_ * DE_];
__device__ __align__(16) __half g_WprTt [2ull * DE_ * DP_];
__device__ __align__(16) __half g_WprTb [2ull * DE_ * DP_];

__device__ __align__(16) float  g_Kpr   [(size_t)LC_ * DP_];
__device__ __align__(16) __half g_Kprhl [2ull * LC_ * DP_];
__device__ __align__(16) __half g_P1Thl [2ull * LC_ * DP_];
__device__ __align__(16) __half g_P2Thl [2ull * DE_ * LC_];
__device__ __align__(16) float  g_att   [(size_t)MPR * LC_];
__device__ __align__(16) __half g_atthl [(size_t)MPR * LC_];      // hi only
__device__ __align__(16) float  g_bqrow [LC_];

__device__ __align__(16) float  g_Kdr   [(size_t)LC_ * DE_];
__device__ __align__(16) __half g_Kdrhl [2ull * LC_ * DE_];
__device__ __align__(16) __half g_KdrT  [2ull * DE_ * LC_];
__device__ __align__(16) __half g_P1dThl[2ull * LC_ * DE_];
__device__ __align__(16) float  g_attdr [(size_t)MDR * LC_];
__device__ __align__(16) __half g_attdrhl[(size_t)MDR * LC_];     // hi only
__device__ __align__(16) float  g_bq2row[LC_];

// ---------------------------------------------------------------------------
// mma.sync fp16 GEMM: C = alpha * A*B^T (+bias), hi/lo split accumulation.
// nC=3: (Ah,Bh),(Ah,Bl),(Al,Bh)   nC=2: (Ah,Bh),(Ah,Bl)
// A:[M,K], B:[N,K] row-major fp16. Block tile 128x128, K-stage 32.
// THREE-stage cp.async ring (2 stages of prefetch distance), 2 CTAs/SM.
// ---------------------------------------------------------------------------
#define ROWB 80
#define ASTG (128 * ROWB)          // 10240 B per operand per stage
#define STAGE (2 * ASTG)           // A+B per stage
#define SMEM3 (3 * STAGE)          // 61440 B dynamic

__global__ __launch_bounds__(256) void gemm_mma(
    const __half* __restrict__ A, size_t aLo,
    const __half* __restrict__ Bm, size_t bLo,
    int K, int nC,
    float* __restrict__ outF, int accumF, int ldcF,
    __half* __restrict__ outH, size_t outLoH, int ldcH,
    const float* __restrict__ bias, float alpha)
{
    extern __shared__ __align__(16) char smem[];
    const uint32_t sBase = smem_u32(smem);

    const int tid = threadIdx.x;
    const int lane = tid & 31;
    const int warp = tid >> 5;
    const int m0 = blockIdx.y * 128;
    const int n0 = blockIdx.x * 128;
    const int wm = (warp & 1) * 64;
    const int wn = (warp >> 1) * 32;

    const __half* Ap[3] = {A, A, A + aLo};
    const __half* Bp[3] = {Bm, Bm + bLo, Bm};

    const int Ks = K >> 5;
    const int total = nC * Ks;

    const int lr0 = tid >> 2;
    const int lc0 = (tid & 3) * 16;

    const int arow = lane & 15;
    const int acol = (lane >> 4) * 16;
    uint32_t aBase[4];
    #pragma unroll
    for (int i = 0; i < 4; i++)
        aBase[i] = sBase + (wm + 16 * i + arow) * ROWB + acol;
    const int brow = (lane & 7) + ((lane >> 4) & 1) * 8;
    const int bcol = ((lane >> 3) & 1) * 16;
    uint32_t bBase[2];
    #pragma unroll
    for (int j = 0; j < 2; j++)
        bBase[j] = sBase + ASTG + (wn + 16 * j + brow) * ROWB + bcol;

    float acc[4][4][4];
    #pragma unroll
    for (int i = 0; i < 4; i++)
        #pragma unroll
        for (int j = 0; j < 4; j++)
            #pragma unroll
            for (int e = 0; e < 4; e++) acc[i][j][e] = 0.0f;

    auto load_stage = [&](int s) {
        const int p = s / Ks;
        const int t = s - p * Ks;
        const int buf = s % 3;
        const char* Ag = (const char*)Ap[p];
        const char* Bg = (const char*)Bp[p];
        const size_t kb = (size_t)t * 64;
        #pragma unroll
        for (int h = 0; h < 2; h++) {
            const int row = lr0 + h * 64;
            const uint32_t so = buf * STAGE + row * ROWB + lc0;
            cpa16(sBase + so, Ag + ((size_t)(m0 + row) * K) * 2 + kb + lc0);
            cpa16(sBase + ASTG + so, Bg + ((size_t)(n0 + row) * K) * 2 + kb + lc0);
        }
        CP_COMMIT();
    };

    load_stage(0);
    if (total > 1) load_stage(1);
    if (total > 2) load_stage(2);

    for (int s = 0; s < total; s++) {
        // stages issued: min(total, s+3); make stage s visible
        if (s + 2 < total)      { CP_WAIT2(); }
        else if (s + 1 < total) { CP_WAIT1(); }
        else                    { CP_WAIT0(); }
        __syncthreads();

        const uint32_t off = (s % 3) * STAGE;
        #pragma unroll
        for (int kstep = 0; kstep < 2; kstep++) {
            uint32_t aF[4][4], bF[2][4];
            #pragma unroll
            for (int i = 0; i < 4; i++)
                LDSM4(aF[i], aBase[i] + off + kstep * 32);
            #pragma unroll
            for (int j = 0; j < 2; j++)
                LDSM4(bF[j], bBase[j] + off + kstep * 32);
            #pragma unroll
            for (int i = 0; i < 4; i++)
                #pragma unroll
                for (int j = 0; j < 4; j++) {
                    uint32_t bb[2] = {bF[j >> 1][(j & 1) * 2],
                                      bF[j >> 1][(j & 1) * 2 + 1]};
                    MMA16816(acc[i][j], aF[i], bb);
                }
        }
        __syncthreads();
        if (s + 3 < total) load_stage(s + 3);
    }

    const int mrow = m0 + wm + (lane >> 2);
    const int ncb  = n0 + wn + 2 * (lane & 3);

    #pragma unroll
    for (int j = 0; j < 4; j++) {
        const int n = ncb + 8 * j;
        float badd0 = 0.0f, badd1 = 0.0f;
        if (bias) { badd0 = bias[n]; badd1 = bias[n + 1]; }
        #pragma unroll
        for (int i = 0; i < 4; i++) {
            #pragma unroll
            for (int half_ = 0; half_ < 2; half_++) {
                const int m = mrow + 16 * i + 8 * half_;
                float v0 = acc[i][j][2 * half_ + 0] * alpha + badd0;
                float v1 = acc[i][j][2 * half_ + 1] * alpha + badd1;
                if (outH) {
                    const size_t base = (size_t)m * ldcH + n;
                    const __half h0 = __float2half(v0);
                    const __half h1 = __float2half(v1);
                    const __half l0 = __float2half(v0 - __half2float(h0));
                    const __half l1 = __float2half(v1 - __half2float(h1));
                    *(__half2*)&outH[base] = __halves2half2(h0, h1);
                    *(__half2*)&outH[base + outLoH] = __halves2half2(l0, l1);
                }
                if (outF) {
                    const size_t base = (size_t)m * ldcF + n;
                    if (accumF) {
                        float2 o = *(float2*)&outF[base];
                        v0 += o.x; v1 += o.y;
                    }
                    float2 w; w.x = v0; w.y = v1;
                    *(float2*)&outF[base] = w;
                }
            }
        }
    }
}

// ---------------------------------------------------------------------------
// fp32 -> fp16 hi/lo split
// ---------------------------------------------------------------------------
__global__ __launch_bounds__(256) void split_k(
    const float* __restrict__ in, __half* __restrict__ oh,
    size_t loOff, int n4)
{
    const int i = blockIdx.x * blockDim.x + threadIdx.x;
    if (i >= n4) return;
    const float4 v = ((const float4*)in)[i];
    const float vv[4] = {v.x, v.y, v.z, v.w};
    __half h[4], l[4];
    #pragma unroll
    for (int j = 0; j < 4; j++) {
        h[j] = __float2half(vv[j]);
        l[j] = __float2half(vv[j] - __half2float(h[j]));
    }
    *(uint2*)&oh[(size_t)i * 4]         = *(uint2*)h;
    *(uint2*)&oh[loOff + (size_t)i * 4] = *(uint2*)l;
}

// fp32 -> fp16 hi only
__global__ __launch_bounds__(256) void split_h(
    const float* __restrict__ in, __half* __restrict__ oh, int n4)
{
    const int i = blockIdx.x * blockDim.x + threadIdx.x;
    if (i >= n4) return;
    const float4 v = ((const float4*)in)[i];
    __half h[4];
    h[0] = __float2half(v.x); h[1] = __float2half(v.y);
    h[2] = __float2half(v.z); h[3] = __float2half(v.w);
    *(uint2*)&oh[(size_t)i * 4] = *(uint2*)h;
}

// ---------------------------------------------------------------------------
// fp32 [R,C] -> transposed fp16 hi/lo [C,R]
// ---------------------------------------------------------------------------
__global__ __launch_bounds__(256) void tsplit_k(
    const float* __restrict__ in, int R, int C,
    __half* __restrict__ oh, size_t loOff)
{
    __shared__ float t[32][33];
    const int c0 = blockIdx.x * 32;
    const int rr0 = blockIdx.y * 32;
    const int tx = threadIdx.x;
    const int ty = threadIdx.y;
    #pragma unroll
    for (int i = 0; i < 4; i++)
        t[ty + 8 * i][tx] = in[(size_t)(rr0 + ty + 8 * i) * C + c0 + tx];
    __syncthreads();
    #pragma unroll
    for (int i = 0; i < 4; i++) {
        const float v = t[tx][ty + 8 * i];
        const __half hh = __float2half(v);
        const __half ll = __float2half(v - __half2float(hh));
        const size_t o = (size_t)(c0 + ty + 8 * i) * R + rr0 + tx;
        oh[o] = hh;
        oh[loOff + o] = ll;
    }
}

// ---------------------------------------------------------------------------
// out[c] = alpha * dot(bvec, Kmat[c,:])
// ---------------------------------------------------------------------------
__global__ __launch_bounds__(256) void bias_row_k(
    const float* __restrict__ bvec, const float* __restrict__ Kmat,
    int K, float alpha, float* __restrict__ outv)
{
    const int c = blockIdx.x;
    const int tid = threadIdx.x;
    float s = 0.0f;
    for (int k = tid; k < K; k += 256)
        s += bvec[k] * Kmat[(size_t)c * K + k];
    __shared__ float red[8];
    const int lane = tid & 31;
    const int warp = tid >> 5;
    #pragma unroll
    for (int o = 16; o > 0; o >>= 1)
        s += __shfl_xor_sync(0xffffffffu, s, o);
    if (lane == 0) red[warp] = s;
    __syncthreads();
    if (tid == 0) {
        float t = 0.0f;
        #pragma unroll
        for (int i = 0; i < 8; i++) t += red[i];
        outv[c] = t * alpha;
    }
}

// ---------------------------------------------------------------------------
// Masked softmax (LC=256 cols) -> fp16 hi
// ---------------------------------------------------------------------------
__global__ __launch_bounds__(256) void softmax_split_k(
    const float* __restrict__ att, const int* __restrict__ mask,
    __half* __restrict__ oh)
{
    const int row = blockIdx.x;
    const int c = threadIdx.x;
    const size_t idx = (size_t)row * LC_ + c;

    float v = att[idx];
    if (mask[row] != 0) v = -1e10f;

    __shared__ float red_max[8];
    __shared__ float red_sum[8];
    const int lane = c & 31;
    const int warp = c >> 5;

    float m = v;
    #pragma unroll
    for (int o = 16; o > 0; o >>= 1)
        m = fmaxf(m, __shfl_xor_sync(0xffffffffu, m, o));
    if (lane == 0) red_max[warp] = m;
    __syncthreads();
    float mmax = red_max[0];
    #pragma unroll
    for (int i = 1; i < 8; i++) mmax = fmaxf(mmax, red_max[i]);

    const float e = expf(v - mmax);

    float s = e;
    #pragma unroll
    for (int o = 16; o > 0; o >>= 1)
        s += __shfl_xor_sync(0xffffffffu, s, o);
    if (lane == 0) red_sum[warp] = s;
    __syncthreads();
    float ssum = red_sum[0];
    #pragma unroll
    for (int i = 1; i < 8; i++) ssum += red_sum[i];

    oh[idx] = __float2half(e / ssum);
}

// ---------------------------------------------------------------------------
// Copy drug_f into first half of drug output rows
// ---------------------------------------------------------------------------
__global__ __launch_bounds__(256) void copy_drug_kernel(
    const float* __restrict__ drug_f, float* __restrict__ out)
{
    const int idx = blockIdx.x * blockDim.x + threadIdx.x;
    if (idx >= MDR * (DE_ / 4)) return;
    const int m = idx / (DE_ / 4);
    const int n4 = idx % (DE_ / 4);
    const float4 v = ((const float4*)drug_f)[(size_t)m * (DE_ / 4) + n4];
    ((float4*)out)[(size_t)m * (2 * DE_ / 4) + n4] = v;
}

// ---------------------------------------------------------------------------
// Launch — forked multi-stream graph
// ---------------------------------------------------------------------------
static inline void* sym(const void* s) {
    void* p = 0;
    cudaGetSymbolAddress(&p, s);
    return p;
}

extern "C" void kernel_launch(void* const* d_in, const int* in_sizes, int n_in,
                              void* d_out, int out_size)
{
    const float* pr_f    = (const float*)d_in[0];
    const float* drug_f  = (const float*)d_in[1];
    const float* pr_conf = (const float*)d_in[2];
    const float* dr_conf = (const float*)d_in[3];
    const float* Wq  = (const float*)d_in[4];
    const float* bq  = (const float*)d_in[5];
    const float* Wk  = (const float*)d_in[6];
    const float* bk  = (const float*)d_in[7];
    const float* Wq2 = (const float*)d_in[8];
    const float* bq2 = (const float*)d_in[9];
    const float* Wk2 = (const float*)d_in[10];
    const float* bk2 = (const float*)d_in[11];
    const float* Wpr = (const float*)d_in[12];
    const float* bpr = (const float*)d_in[13];
    const int* pmask = (const int*)d_in[14];
    const int* dmask = (const int*)d_in[15];

    float* out    = (float*)d_out;
    float* pr_out = out;                                  // [16384, 512]
    float* dr_out = out + (size_t)MPR * DE_;              // [4096, 1024]

    __half* prf    = (__half*)sym(g_prf);
    __half* drugf  = (__half*)sym(g_drugf);
    __half* prconf = (__half*)sym(g_prconf);
    __half* drconf = (__half*)sym(g_drconf);
    __half* Wqhl   = (__half*)sym(g_Wqhl);
    __half* WkT    = (__half*)sym(g_WkT);
    __half* Wq2hl  = (__half*)sym(g_Wq2hl);
    __half* Wk2T   = (__half*)sym(g_Wk2T);
    __half* WprTt  = (__half*)sym(g_WprTt);
    __half* WprTb  = (__half*)sym(g_WprTb);
    float*  Kpr    = (float*)sym(g_Kpr);
    __half* Kprhl  = (__half*)sym(g_Kprhl);
    __half* P1Thl  = (__half*)sym(g_P1Thl);
    __half* P2Thl  = (__half*)sym(g_P2Thl);
    float*  att    = (float*)sym(g_att);
    __half* atthl  = (__half*)sym(g_atthl);
    float*  bqrow  = (float*)sym(g_bqrow);
    float*  Kdr    = (float*)sym(g_Kdr);
    __half* Kdrhl  = (__half*)sym(g_Kdrhl);
    __half* KdrT   = (__half*)sym(g_KdrT);
    __half* P1dThl = (__half*)sym(g_P1dThl);
    float*  attdr  = (float*)sym(g_attdr);
    __half* attdrhl= (__half*)sym(g_attdrhl);
    float*  bq2row = (float*)sym(g_bq2row);

    const float pr_alpha = 1.0f / 16.0f;
    const float dr_alpha = 1.0f / sqrtf((float)DE_);

    cudaFuncSetAttribute(gemm_mma,
                         cudaFuncAttributeMaxDynamicSharedMemorySize, SMEM3);

    cudaStream_t s1, s2;
    cudaStreamCreateWithFlags(&s1, cudaStreamNonBlocking);
    cudaStreamCreateWithFlags(&s2, cudaStreamNonBlocking);
    cudaEvent_t evStart, evA, evQ, evJ1, evJ2;
    cudaEventCreateWithFlags(&evStart, cudaEventDisableTiming);
    cudaEventCreateWithFlags(&evA, cudaEventDisableTiming);
    cudaEventCreateWithFlags(&evQ, cudaEventDisableTiming);
    cudaEventCreateWithFlags(&evJ1, cudaEventDisableTiming);
    cudaEventCreateWithFlags(&evJ2, cudaEventDisableTiming);

    cudaEventRecord(evStart, 0);
    cudaStreamWaitEvent(s1, evStart, 0);
    cudaStreamWaitEvent(s2, evStart, 0);

    // ======== stream s1: pr_f hi-split -> prout1 (big independent GEMM) =====
    {
        const int n4 = MPR * DP_ / 4;
        split_h<<<(n4 + 255) / 256, 256, 0, s1>>>(pr_f, prf, n4);
        cudaEventRecord(evA, s1);     // prf ready
        tsplit_k<<<dim3(DE_ / 32, DP_ / 32), dim3(32, 8), 0, s1>>>(
            Wpr, DP_, DE_, WprTt, (size_t)DE_ * DP_);
        // prout1 = pr_f @ WprTop + bpr   (2-combo)
        gemm_mma<<<dim3(DE_ / 128, MPR / 128), 256, SMEM3, s1>>>(
            prf, 0, WprTt, (size_t)DE_ * DP_, DP_, 2,
            pr_out, 0, DE_, (__half*)0, 0, 0, bpr, 1.0f);
        cudaEventRecord(evQ, s1);     // pr_out base ready
        copy_drug_kernel<<<(MDR * (DE_ / 4) + 255) / 256, 256, 0, s1>>>(drug_f, dr_out);
        cudaEventRecord(evJ1, s1);
    }

    // ======== stream s2: entire drug path ========
    {
        int n4 = MDR * DE_ / 4;
        split_h<<<(n4 + 255) / 256, 256, 0, s2>>>(drug_f, drugf, n4);
        n4 = LC_ * DE_ / 4;
        split_k<<<(n4 + 255) / 256, 256, 0, s2>>>(dr_conf, drconf, (size_t)LC_ * DE_, n4);
        n4 = DE_ * DE_ / 4;
        split_k<<<(n4 + 255) / 256, 256, 0, s2>>>(Wq2, Wq2hl, (size_t)DE_ * DE_, n4);
        tsplit_k<<<dim3(DE_ / 32, DE_ / 32), dim3(32, 8), 0, s2>>>(
            Wk2, DE_, DE_, Wk2T, (size_t)DE_ * DE_);
        // Kdr = dr_conf @ Wk2 + bk2 (3-combo; f32 + hi/lo out)
        gemm_mma<<<dim3(DE_ / 128, LC_ / 128), 256, SMEM3, s2>>>(
            drconf, (size_t)LC_ * DE_, Wk2T, (size_t)DE_ * DE_, DE_, 3,
            Kdr, 0, DE_, Kdrhl, (size_t)LC_ * DE_, DE_, bk2, 1.0f);
        tsplit_k<<<dim3(DE_ / 32, LC_ / 32), dim3(32, 8), 0, s2>>>(
            Kdr, LC_, DE_, KdrT, (size_t)DE_ * LC_);
        // P1dT = Kdr @ Wq2^T (3-combo; hi/lo only)
        gemm_mma<<<dim3(DE_ / 128, LC_ / 128), 256, SMEM3, s2>>>(
            Kdrhl, (size_t)LC_ * DE_, Wq2hl, (size_t)DE_ * DE_, DE_, 3,
            (float*)0, 0, 0, P1dThl, (size_t)LC_ * DE_, DE_, (const float*)0, 1.0f);
        bias_row_k<<<LC_, 256, 0, s2>>>(bq2, Kdr, DE_, dr_alpha, bq2row);
        // att_dr = drug_f @ P1dT^T * dr_alpha + bq2row   (2-combo)
        gemm_mma<<<dim3(LC_ / 128, MDR / 128), 256, SMEM3, s2>>>(
            drugf, 0, P1dThl, (size_t)LC_ * DE_, DE_, 2,
            attdr, 0, LC_, (__half*)0, 0, 0, bq2row, dr_alpha);
        softmax_split_k<<<MDR, 256, 0, s2>>>(attdr, dmask, attdrhl);
        // dr_out[:, 512:] = S_dr @ Kdr   (2-combo)
        gemm_mma<<<dim3(DE_ / 128, MDR / 128), 256, SMEM3, s2>>>(
            attdrhl, 0, KdrT, (size_t)DE_ * LC_, LC_, 2,
            dr_out + DE_, 0, 2 * DE_, (__half*)0, 0, 0, (const float*)0, 1.0f);
        cudaEventRecord(evJ2, s2);
    }

    // ======== stream 0: protein attention chain ========
    {
        int n4 = LC_ * DP_ / 4;
        split_k<<<(n4 + 255) / 256, 256>>>(pr_conf, prconf, (size_t)LC_ * DP_, n4);
        tsplit_k<<<dim3(DP_ / 32, DP_ / 32), dim3(32, 8)>>>(
            Wk, DP_, DP_, WkT, (size_t)DP_ * DP_);
        n4 = DP_ * DP_ / 4;
        split_k<<<(n4 + 255) / 256, 256>>>(Wq, Wqhl, (size_t)DP_ * DP_, n4);
        tsplit_k<<<dim3(DE_ / 32, DP_ / 32), dim3(32, 8)>>>(
            Wpr + (size_t)DP_ * DE_, DP_, DE_, WprTb, (size_t)DE_ * DP_);
        // Kpr = pr_conf @ Wk + bk (3-combo; f32 + hi/lo)
        gemm_mma<<<dim3(DP_ / 128, LC_ / 128), 256, SMEM3>>>(
            prconf, (size_t)LC_ * DP_, WkT, (size_t)DP_ * DP_, DP_, 3,
            Kpr, 0, DP_, Kprhl, (size_t)LC_ * DP_, DP_, bk, 1.0f);
        // P1T = Kpr @ Wq^T (3-combo; hi/lo only)
        gemm_mma<<<dim3(DP_ / 128, LC_ / 128), 256, SMEM3>>>(
            Kprhl, (size_t)LC_ * DP_, Wqhl, (size_t)DP_ * DP_, DP_, 3,
            (float*)0, 0, 0, P1Thl, (size_t)LC_ * DP_, DP_, (const float*)0, 1.0f);
        // P2T = WprBot contracted with Kpr (3-combo; hi/lo only)
        gemm_mma<<<dim3(LC_ / 128, DE_ / 128), 256, SMEM3>>>(
            WprTb, (size_t)DE_ * DP_, Kprhl, (size_t)LC_ * DP_, DP_, 3,
            (float*)0, 0, 0, P2Thl, (size_t)DE_ * LC_, LC_, (const float*)0, 1.0f);
        bias_row_k<<<LC_, 256>>>(bq, Kpr, DP_, pr_alpha, bqrow);
        // att = pr_f @ P1T^T / 16 + bqrow  (2-combo; needs prf from s1)
        cudaStreamWaitEvent(0, evA, 0);
        gemm_mma<<<dim3(LC_ / 128, MPR / 128), 256, SMEM3>>>(
            prf, 0, P1Thl, (size_t)LC_ * DP_, DP_, 2,
            att, 0, LC_, (__half*)0, 0, 0, bqrow, pr_alpha);
        softmax_split_k<<<MPR, 256>>>(att, pmask, atthl);
        // pr_out += S @ P2T^T  (2-combo; needs prout1 from s1)
        cudaStreamWaitEvent(0, evQ, 0);
        gemm_mma<<<dim3(DE_ / 128, MPR / 128), 256, SMEM3>>>(
            atthl, 0, P2Thl, (size_t)DE_ * LC_, LC_, 2,
            pr_out, 1, DE_, (__half*)0, 0, 0, (const float*)0, 1.0f);
    }

    cudaStreamWaitEvent(0, evJ1, 0);
    cudaStreamWaitEvent(0, evJ2, 0);

    cudaEventDestroy(evStart);
    cudaEventDestroy(evA);
    cudaEventDestroy(evQ);
    cudaEventDestroy(evJ1);
    cudaEventDestroy(evJ2);
    cudaStreamDestroy(s1);
    cudaStreamDestroy(s2);
}

// round 14
// speedup vs baseline: 1.7507x; 1.7507x over previous
#include <cuda_runtime.h>
#include <cuda_fp16.h>
#include <cstdint>
#include <math.h>

// ---------------------------------------------------------------------------
// Problem constants
// ---------------------------------------------------------------------------
#define B_   16
#define LP_  1024
#define LD_  256
#define DP_  1280
#define DE_  512
#define LC_  256

#define MPR  (B_ * LP_)      // 16384
#define MDR  (B_ * LD_)      // 4096

// ---------------------------------------------------------------------------
// Helpers
// ---------------------------------------------------------------------------
__device__ __forceinline__ uint32_t smem_u32(const void* p) {
    uint32_t a;
    asm("{ .reg .u64 t; cvta.to.shared.u64 t, %1; cvt.u32.u64 %0, t; }"
        : "=r"(a) : "l"(p));
    return a;
}

__device__ __forceinline__ void cpa16(uint32_t saddr, const void* g) {
    asm volatile("cp.async.cg.shared.global [%0], [%1], 16;"
                 :: "r"(saddr), "l"(g) : "memory");
}
#define CP_COMMIT() asm volatile("cp.async.commit_group;" ::: "memory")
#define CP_WAIT0()  asm volatile("cp.async.wait_group 0;" ::: "memory")
#define CP_WAIT1()  asm volatile("cp.async.wait_group 1;" ::: "memory")

#define LDSM4(r, addr) \
    asm volatile("ldmatrix.sync.aligned.m8n8.x4.shared.b16 {%0,%1,%2,%3}, [%4];" \
        : "=r"((r)[0]), "=r"((r)[1]), "=r"((r)[2]), "=r"((r)[3]) : "r"(addr))

#define MMA16816(d, a, b) \
    asm volatile("mma.sync.aligned.m16n8k16.row.col.f32.f16.f16.f32 " \
        "{%0,%1,%2,%3}, {%4,%5,%6,%7}, {%8,%9}, {%0,%1,%2,%3};" \
        : "+f"((d)[0]), "+f"((d)[1]), "+f"((d)[2]), "+f"((d)[3]) \
        : "r"((a)[0]), "r"((a)[1]), "r"((a)[2]), "r"((a)[3]), \
          "r"((b)[0]), "r"((b)[1]))

// ---------------------------------------------------------------------------
// Scratch (fp16; hl buffers: hi at [0,sz), lo at [sz,2sz)); 16B aligned
// ---------------------------------------------------------------------------
__device__ __align__(16) __half g_prf   [(size_t)MPR * DP_];      // hi only
__device__ __align__(16) __half g_drugf [(size_t)MDR * DE_];      // hi only
__device__ __align__(16) __half g_prconf[2ull * LC_ * DP_];
__device__ __align__(16) __half g_drconf[2ull * LC_ * DE_];
__device__ __align__(16) __half g_Wqhl  [2ull * DP_ * DP_];
__device__ __align__(16) __half g_WkT   [2ull * DP_ * DP_];
__device__ __align__(16) __half g_Wq2hl [2ull * DE_ * DE_];
__device__ __align__(16) __half g_Wk2T  [2ull * DE_ * DE_];
__device__ __align__(16) __half g_WprTt [2ull * DE_ * DP_];
__device__ __align__(16) __half g_WprTb [2ull * DE_ * DP_];

__device__ __align__(16) float  g_Kpr   [(size_t)LC_ * DP_];
__device__ __align__(16) __half g_Kprhl [2ull * LC_ * DP_];
__device__ __align__(16) __half g_P1Thl [2ull * LC_ * DP_];
__device__ __align__(16) __half g_P2Thl [2ull * DE_ * LC_];
__device__ __align__(16) float  g_att   [(size_t)MPR * LC_];
__device__ __align__(16) __half g_atthl [(size_t)MPR * LC_];      // hi only
__device__ __align__(16) float  g_bqrow [LC_];

__device__ __align__(16) float  g_Kdr   [(size_t)LC_ * DE_];
__device__ __align__(16) __half g_Kdrhl [2ull * LC_ * DE_];
__device__ __align__(16) __half g_KdrT  [2ull * DE_ * LC_];
__device__ __align__(16) __half g_P1dThl[2ull * LC_ * DE_];
__device__ __align__(16) float  g_attdr [(size_t)MDR * LC_];
__device__ __align__(16) __half g_attdrhl[(size_t)MDR * LC_];     // hi only
__device__ __align__(16) float  g_bq2row[LC_];

// ---------------------------------------------------------------------------
// mma.sync fp16 GEMM: C = alpha * A*B^T (+bias), hi/lo split accumulation.
// nC=3: (Ah,Bh),(Ah,Bl),(Al,Bh)   nC=2: (Ah,Bh),(Ah,Bl)   nC=1: (Ah,Bh)
// A:[M,K], B:[N,K] row-major fp16. Tile 128x128, K-stage 32, double-buffered.
// (R7 core — proven fastest config; do not touch.)
// ---------------------------------------------------------------------------
#define STG 10240
#define ROWB 80

__global__ __launch_bounds__(256) void gemm_mma(
    const __half* __restrict__ A, size_t aLo,
    const __half* __restrict__ Bm, size_t bLo,
    int K, int nC,
    float* __restrict__ outF, int accumF, int ldcF,
    __half* __restrict__ outH, size_t outLoH, int ldcH,
    const float* __restrict__ bias, float alpha)
{
    __shared__ __align__(16) char smem[4 * STG];
    const uint32_t sA = smem_u32(smem);
    const uint32_t sB = sA + 2 * STG;

    const int tid = threadIdx.x;
    const int lane = tid & 31;
    const int warp = tid >> 5;
    const int m0 = blockIdx.y * 128;
    const int n0 = blockIdx.x * 128;
    const int wm = (warp & 1) * 64;
    const int wn = (warp >> 1) * 32;

    const __half* Ap[3] = {A, A, A + aLo};
    const __half* Bp[3] = {Bm, Bm + bLo, Bm};

    const int Ks = K >> 5;
    const int total = nC * Ks;

    const int lr0 = tid >> 2;
    const int lc0 = (tid & 3) * 16;

    const int arow = lane & 15;
    const int acol = (lane >> 4) * 16;
    uint32_t aBase[4];
    #pragma unroll
    for (int i = 0; i < 4; i++)
        aBase[i] = sA + (wm + 16 * i + arow) * ROWB + acol;
    const int brow = (lane & 7) + ((lane >> 4) & 1) * 8;
    const int bcol = ((lane >> 3) & 1) * 16;
    uint32_t bBase[2];
    #pragma unroll
    for (int j = 0; j < 2; j++)
        bBase[j] = sB + (wn + 16 * j + brow) * ROWB + bcol;

    float acc[4][4][4];
    #pragma unroll
    for (int i = 0; i < 4; i++)
        #pragma unroll
        for (int j = 0; j < 4; j++)
            #pragma unroll
            for (int e = 0; e < 4; e++) acc[i][j][e] = 0.0f;

    auto load_stage = [&](int s) {
        const int p = s / Ks;
        const int t = s - p * Ks;
        const int buf = s & 1;
        const char* Ag = (const char*)Ap[p];
        const char* Bg = (const char*)Bp[p];
        const size_t kb = (size_t)t * 64;
        #pragma unroll
        for (int h = 0; h < 2; h++) {
            const int row = lr0 + h * 64;
            const uint32_t sa = buf * STG + row * ROWB + lc0;
            cpa16(sA + sa, Ag + ((size_t)(m0 + row) * K) * 2 + kb + lc0);
            cpa16(sB + sa, Bg + ((size_t)(n0 + row) * K) * 2 + kb + lc0);
        }
        CP_COMMIT();
    };

    load_stage(0);
    load_stage(1);

    for (int s = 0; s < total; s++) {
        if (s + 1 < total) { CP_WAIT1(); } else { CP_WAIT0(); }
        __syncthreads();

        const int buf = s & 1;
        const uint32_t off = buf * STG;
        #pragma unroll
        for (int kstep = 0; kstep < 2; kstep++) {
            uint32_t aF[4][4], bF[2][4];
            #pragma unroll
            for (int i = 0; i < 4; i++)
                LDSM4(aF[i], aBase[i] + off + kstep * 32);
            #pragma unroll
            for (int j = 0; j < 2; j++)
                LDSM4(bF[j], bBase[j] + off + kstep * 32);
            #pragma unroll
            for (int i = 0; i < 4; i++)
                #pragma unroll
                for (int j = 0; j < 4; j++) {
                    uint32_t bb[2] = {bF[j >> 1][(j & 1) * 2],
                                      bF[j >> 1][(j & 1) * 2 + 1]};
                    MMA16816(acc[i][j], aF[i], bb);
                }
        }
        __syncthreads();
        if (s + 2 < total) load_stage(s + 2);
    }

    const int mrow = m0 + wm + (lane >> 2);
    const int ncb  = n0 + wn + 2 * (lane & 3);

    #pragma unroll
    for (int j = 0; j < 4; j++) {
        const int n = ncb + 8 * j;
        float badd0 = 0.0f, badd1 = 0.0f;
        if (bias) { badd0 = bias[n]; badd1 = bias[n + 1]; }
        #pragma unroll
        for (int i = 0; i < 4; i++) {
            #pragma unroll
            for (int half_ = 0; half_ < 2; half_++) {
                const int m = mrow + 16 * i + 8 * half_;
                float v0 = acc[i][j][2 * half_ + 0] * alpha + badd0;
                float v1 = acc[i][j][2 * half_ + 1] * alpha + badd1;
                if (outH) {
                    const size_t base = (size_t)m * ldcH + n;
                    const __half h0 = __float2half(v0);
                    const __half h1 = __float2half(v1);
                    const __half l0 = __float2half(v0 - __half2float(h0));
                    const __half l1 = __float2half(v1 - __half2float(h1));
                    *(__half2*)&outH[base] = __halves2half2(h0, h1);
                    *(__half2*)&outH[base + outLoH] = __halves2half2(l0, l1);
                }
                if (outF) {
                    const size_t base = (size_t)m * ldcF + n;
                    if (accumF) {
                        float2 o = *(float2*)&outF[base];
                        v0 += o.x; v1 += o.y;
                    }
                    float2 w; w.x = v0; w.y = v1;
                    *(float2*)&outF[base] = w;
                }
            }
        }
    }
}

// ---------------------------------------------------------------------------
// fp32 -> fp16 hi/lo split
// ---------------------------------------------------------------------------
__global__ __launch_bounds__(256) void split_k(
    const float* __restrict__ in, __half* __restrict__ oh,
    size_t loOff, int n4)
{
    const int i = blockIdx.x * blockDim.x + threadIdx.x;
    if (i >= n4) return;
    const float4 v = ((const float4*)in)[i];
    const float vv[4] = {v.x, v.y, v.z, v.w};
    __half h[4], l[4];
    #pragma unroll
    for (int j = 0; j < 4; j++) {
        h[j] = __float2half(vv[j]);
        l[j] = __float2half(vv[j] - __half2float(h[j]));
    }
    *(uint2*)&oh[(size_t)i * 4]         = *(uint2*)h;
    *(uint2*)&oh[loOff + (size_t)i * 4] = *(uint2*)l;
}

// fp32 -> fp16 hi only
__global__ __launch_bounds__(256) void split_h(
    const float* __restrict__ in, __half* __restrict__ oh, int n4)
{
    const int i = blockIdx.x * blockDim.x + threadIdx.x;
    if (i >= n4) return;
    const float4 v = ((const float4*)in)[i];
    __half h[4];
    h[0] = __float2half(v.x); h[1] = __float2half(v.y);
    h[2] = __float2half(v.z); h[3] = __float2half(v.w);
    *(uint2*)&oh[(size_t)i * 4] = *(uint2*)h;
}

// ---------------------------------------------------------------------------
// fp32 [R,C] -> transposed fp16 hi/lo [C,R]
// ---------------------------------------------------------------------------
__global__ __launch_bounds__(256) void tsplit_k(
    const float* __restrict__ in, int R, int C,
    __half* __restrict__ oh, size_t loOff)
{
    __shared__ float t[32][33];
    const int c0 = blockIdx.x * 32;
    const int rr0 = blockIdx.y * 32;
    const int tx = threadIdx.x;
    const int ty = threadIdx.y;
    #pragma unroll
    for (int i = 0; i < 4; i++)
        t[ty + 8 * i][tx] = in[(size_t)(rr0 + ty + 8 * i) * C + c0 + tx];
    __syncthreads();
    #pragma unroll
    for (int i = 0; i < 4; i++) {
        const float v = t[tx][ty + 8 * i];
        const __half hh = __float2half(v);
        const __half ll = __float2half(v - __half2float(hh));
        const size_t o = (size_t)(c0 + ty + 8 * i) * R + rr0 + tx;
        oh[o] = hh;
        oh[loOff + o] = ll;
    }
}

// ---------------------------------------------------------------------------
// out[c] = alpha * dot(bvec, Kmat[c,:])
// ---------------------------------------------------------------------------
__global__ __launch_bounds__(256) void bias_row_k(
    const float* __restrict__ bvec, const float* __restrict__ Kmat,
    int K, float alpha, float* __restrict__ outv)
{
    const int c = blockIdx.x;
    const int tid = threadIdx.x;
    float s = 0.0f;
    for (int k = tid; k < K; k += 256)
        s += bvec[k] * Kmat[(size_t)c * K + k];
    __shared__ float red[8];
    const int lane = tid & 31;
    const int warp = tid >> 5;
    #pragma unroll
    for (int o = 16; o > 0; o >>= 1)
        s += __shfl_xor_sync(0xffffffffu, s, o);
    if (lane == 0) red[warp] = s;
    __syncthreads();
    if (tid == 0) {
        float t = 0.0f;
        #pragma unroll
        for (int i = 0; i < 8; i++) t += red[i];
        outv[c] = t * alpha;
    }
}

// ---------------------------------------------------------------------------
// Masked softmax (LC=256 cols) -> fp16 hi
// ---------------------------------------------------------------------------
__global__ __launch_bounds__(256) void softmax_split_k(
    const float* __restrict__ att, const int* __restrict__ mask,
    __half* __restrict__ oh)
{
    const int row = blockIdx.x;
    const int c = threadIdx.x;
    const size_t idx = (size_t)row * LC_ + c;

    float v = att[idx];
    if (mask[row] != 0) v = -1e10f;

    __shared__ float red_max[8];
    __shared__ float red_sum[8];
    const int lane = c & 31;
    const int warp = c >> 5;

    float m = v;
    #pragma unroll
    for (int o = 16; o > 0; o >>= 1)
        m = fmaxf(m, __shfl_xor_sync(0xffffffffu, m, o));
    if (lane == 0) red_max[warp] = m;
    __syncthreads();
    float mmax = red_max[0];
    #pragma unroll
    for (int i = 1; i < 8; i++) mmax = fmaxf(mmax, red_max[i]);

    const float e = expf(v - mmax);

    float s = e;
    #pragma unroll
    for (int o = 16; o > 0; o >>= 1)
        s += __shfl_xor_sync(0xffffffffu, s, o);
    if (lane == 0) red_sum[warp] = s;
    __syncthreads();
    float ssum = red_sum[0];
    #pragma unroll
    for (int i = 1; i < 8; i++) ssum += red_sum[i];

    oh[idx] = __float2half(e / ssum);
}

// ---------------------------------------------------------------------------
// Copy drug_f into first half of drug output rows
// ---------------------------------------------------------------------------
__global__ __launch_bounds__(256) void copy_drug_kernel(
    const float* __restrict__ drug_f, float* __restrict__ out)
{
    const int idx = blockIdx.x * blockDim.x + threadIdx.x;
    if (idx >= MDR * (DE_ / 4)) return;
    const int m = idx / (DE_ / 4);
    const int n4 = idx % (DE_ / 4);
    const float4 v = ((const float4*)drug_f)[(size_t)m * (DE_ / 4) + n4];
    ((float4*)out)[(size_t)m * (2 * DE_ / 4) + n4] = v;
}

// ---------------------------------------------------------------------------
// Launch — forked multi-stream graph
// ---------------------------------------------------------------------------
static inline void* sym(const void* s) {
    void* p = 0;
    cudaGetSymbolAddress(&p, s);
    return p;
}

extern "C" void kernel_launch(void* const* d_in, const int* in_sizes, int n_in,
                              void* d_out, int out_size)
{
    const float* pr_f    = (const float*)d_in[0];
    const float* drug_f  = (const float*)d_in[1];
    const float* pr_conf = (const float*)d_in[2];
    const float* dr_conf = (const float*)d_in[3];
    const float* Wq  = (const float*)d_in[4];
    const float* bq  = (const float*)d_in[5];
    const float* Wk  = (const float*)d_in[6];
    const float* bk  = (const float*)d_in[7];
    const float* Wq2 = (const float*)d_in[8];
    const float* bq2 = (const float*)d_in[9];
    const float* Wk2 = (const float*)d_in[10];
    const float* bk2 = (const float*)d_in[11];
    const float* Wpr = (const float*)d_in[12];
    const float* bpr = (const float*)d_in[13];
    const int* pmask = (const int*)d_in[14];
    const int* dmask = (const int*)d_in[15];

    float* out    = (float*)d_out;
    float* pr_out = out;                                  // [16384, 512]
    float* dr_out = out + (size_t)MPR * DE_;              // [4096, 1024]

    __half* prf    = (__half*)sym(g_prf);
    __half* drugf  = (__half*)sym(g_drugf);
    __half* prconf = (__half*)sym(g_prconf);
    __half* drconf = (__half*)sym(g_drconf);
    __half* Wqhl   = (__half*)sym(g_Wqhl);
    __half* WkT    = (__half*)sym(g_WkT);
    __half* Wq2hl  = (__half*)sym(g_Wq2hl);
    __half* Wk2T   = (__half*)sym(g_Wk2T);
    __half* WprTt  = (__half*)sym(g_WprTt);
    __half* WprTb  = (__half*)sym(g_WprTb);
    float*  Kpr    = (float*)sym(g_Kpr);
    __half* Kprhl  = (__half*)sym(g_Kprhl);
    __half* P1Thl  = (__half*)sym(g_P1Thl);
    __half* P2Thl  = (__half*)sym(g_P2Thl);
    float*  att    = (float*)sym(g_att);
    __half* atthl  = (__half*)sym(g_atthl);
    float*  bqrow  = (float*)sym(g_bqrow);
    float*  Kdr    = (float*)sym(g_Kdr);
    __half* Kdrhl  = (__half*)sym(g_Kdrhl);
    __half* KdrT   = (__half*)sym(g_KdrT);
    __half* P1dThl = (__half*)sym(g_P1dThl);
    float*  attdr  = (float*)sym(g_attdr);
    __half* attdrhl= (__half*)sym(g_attdrhl);
    float*  bq2row = (float*)sym(g_bq2row);

    const float pr_alpha = 1.0f / 16.0f;
    const float dr_alpha = 1.0f / sqrtf((float)DE_);

    cudaStream_t s1, s2;
    cudaStreamCreateWithFlags(&s1, cudaStreamNonBlocking);
    cudaStreamCreateWithFlags(&s2, cudaStreamNonBlocking);
    cudaEvent_t evStart, evA, evQ, evJ1, evJ2;
    cudaEventCreateWithFlags(&evStart, cudaEventDisableTiming);
    cudaEventCreateWithFlags(&evA, cudaEventDisableTiming);
    cudaEventCreateWithFlags(&evQ, cudaEventDisableTiming);
    cudaEventCreateWithFlags(&evJ1, cudaEventDisableTiming);
    cudaEventCreateWithFlags(&evJ2, cudaEventDisableTiming);

    cudaEventRecord(evStart, 0);
    cudaStreamWaitEvent(s1, evStart, 0);
    cudaStreamWaitEvent(s2, evStart, 0);

    // ======== stream s1: pr_f hi-split -> prout1 (big independent GEMM) =====
    {
        const int n4 = MPR * DP_ / 4;
        split_h<<<(n4 + 255) / 256, 256, 0, s1>>>(pr_f, prf, n4);
        cudaEventRecord(evA, s1);     // prf ready
        tsplit_k<<<dim3(DE_ / 32, DP_ / 32), dim3(32, 8), 0, s1>>>(
            Wpr, DP_, DE_, WprTt, (size_t)DE_ * DP_);
        // prout1 = pr_f @ WprTop + bpr   (1-combo hi*hi)
        gemm_mma<<<dim3(DE_ / 128, MPR / 128), 256, 0, s1>>>(
            prf, 0, WprTt, (size_t)DE_ * DP_, DP_, 1,
            pr_out, 0, DE_, (__half*)0, 0, 0, bpr, 1.0f);
        cudaEventRecord(evQ, s1);     // pr_out base ready
        copy_drug_kernel<<<(MDR * (DE_ / 4) + 255) / 256, 256, 0, s1>>>(drug_f, dr_out);
        cudaEventRecord(evJ1, s1);
    }

    // ======== stream s2: entire drug path ========
    {
        int n4 = MDR * DE_ / 4;
        split_h<<<(n4 + 255) / 256, 256, 0, s2>>>(drug_f, drugf, n4);
        n4 = LC_ * DE_ / 4;
        split_k<<<(n4 + 255) / 256, 256, 0, s2>>>(dr_conf, drconf, (size_t)LC_ * DE_, n4);
        n4 = DE_ * DE_ / 4;
        split_k<<<(n4 + 255) / 256, 256, 0, s2>>>(Wq2, Wq2hl, (size_t)DE_ * DE_, n4);
        tsplit_k<<<dim3(DE_ / 32, DE_ / 32), dim3(32, 8), 0, s2>>>(
            Wk2, DE_, DE_, Wk2T, (size_t)DE_ * DE_);
        // Kdr = dr_conf @ Wk2 + bk2 (3-combo; f32 + hi/lo out)
        gemm_mma<<<dim3(DE_ / 128, LC_ / 128), 256, 0, s2>>>(
            drconf, (size_t)LC_ * DE_, Wk2T, (size_t)DE_ * DE_, DE_, 3,
            Kdr, 0, DE_, Kdrhl, (size_t)LC_ * DE_, DE_, bk2, 1.0f);
        tsplit_k<<<dim3(DE_ / 32, LC_ / 32), dim3(32, 8), 0, s2>>>(
            Kdr, LC_, DE_, KdrT, (size_t)DE_ * LC_);
        // P1dT = Kdr @ Wq2^T (3-combo; hi/lo only)
        gemm_mma<<<dim3(DE_ / 128, LC_ / 128), 256, 0, s2>>>(
            Kdrhl, (size_t)LC_ * DE_, Wq2hl, (size_t)DE_ * DE_, DE_, 3,
            (float*)0, 0, 0, P1dThl, (size_t)LC_ * DE_, DE_, (const float*)0, 1.0f);
        bias_row_k<<<LC_, 256, 0, s2>>>(bq2, Kdr, DE_, dr_alpha, bq2row);
        // att_dr = drug_f @ P1dT^T * dr_alpha + bq2row   (1-combo)
        gemm_mma<<<dim3(LC_ / 128, MDR / 128), 256, 0, s2>>>(
            drugf, 0, P1dThl, (size_t)LC_ * DE_, DE_, 1,
            attdr, 0, LC_, (__half*)0, 0, 0, bq2row, dr_alpha);
        softmax_split_k<<<MDR, 256, 0, s2>>>(attdr, dmask, attdrhl);
        // dr_out[:, 512:] = S_dr @ Kdr   (1-combo)
        gemm_mma<<<dim3(DE_ / 128, MDR / 128), 256, 0, s2>>>(
            attdrhl, 0, KdrT, (size_t)DE_ * LC_, LC_, 1,
            dr_out + DE_, 0, 2 * DE_, (__half*)0, 0, 0, (const float*)0, 1.0f);
        cudaEventRecord(evJ2, s2);
    }

    // ======== stream 0: protein attention chain ========
    {
        int n4 = LC_ * DP_ / 4;
        split_k<<<(n4 + 255) / 256, 256>>>(pr_conf, prconf, (size_t)LC_ * DP_, n4);
        tsplit_k<<<dim3(DP_ / 32, DP_ / 32), dim3(32, 8)>>>(
            Wk, DP_, DP_, WkT, (size_t)DP_ * DP_);
        n4 = DP_ * DP_ / 4;
        split_k<<<(n4 + 255) / 256, 256>>>(Wq, Wqhl, (size_t)DP_ * DP_, n4);
        tsplit_k<<<dim3(DE_ / 32, DP_ / 32), dim3(32, 8)>>>(
            Wpr + (size_t)DP_ * DE_, DP_, DE_, WprTb, (size_t)DE_ * DP_);
        // Kpr = pr_conf @ Wk + bk (3-combo; f32 + hi/lo)
        gemm_mma<<<dim3(DP_ / 128, LC_ / 128), 256>>>(
            prconf, (size_t)LC_ * DP_, WkT, (size_t)DP_ * DP_, DP_, 3,
            Kpr, 0, DP_, Kprhl, (size_t)LC_ * DP_, DP_, bk, 1.0f);
        // P1T = Kpr @ Wq^T (3-combo; hi/lo only)
        gemm_mma<<<dim3(DP_ / 128, LC_ / 128), 256>>>(
            Kprhl, (size_t)LC_ * DP_, Wqhl, (size_t)DP_ * DP_, DP_, 3,
            (float*)0, 0, 0, P1Thl, (size_t)LC_ * DP_, DP_, (const float*)0, 1.0f);
        // P2T = WprBot contracted with Kpr (3-combo; hi/lo only)
        gemm_mma<<<dim3(LC_ / 128, DE_ / 128), 256>>>(
            WprTb, (size_t)DE_ * DP_, Kprhl, (size_t)LC_ * DP_, DP_, 3,
            (float*)0, 0, 0, P2Thl, (size_t)DE_ * LC_, LC_, (const float*)0, 1.0f);
        bias_row_k<<<LC_, 256>>>(bq, Kpr, DP_, pr_alpha, bqrow);
        // att = pr_f @ P1T^T / 16 + bqrow  (1-combo; needs prf from s1)
        cudaStreamWaitEvent(0, evA, 0);
        gemm_mma<<<dim3(LC_ / 128, MPR / 128), 256>>>(
            prf, 0, P1Thl, (size_t)LC_ * DP_, DP_, 1,
            att, 0, LC_, (__half*)0, 0, 0, bqrow, pr_alpha);
        softmax_split_k<<<MPR, 256>>>(att, pmask, atthl);
        // pr_out += S @ P2T^T  (1-combo; needs prout1 from s1)
        cudaStreamWaitEvent(0, evQ, 0);
        gemm_mma<<<dim3(DE_ / 128, MPR / 128), 256>>>(
            atthl, 0, P2Thl, (size_t)DE_ * LC_, LC_, 1,
            pr_out, 1, DE_, (__half*)0, 0, 0, (const float*)0, 1.0f);
    }

    cudaStreamWaitEvent(0, evJ1, 0);
    cudaStreamWaitEvent(0, evJ2, 0);

    cudaEventDestroy(evStart);
    cudaEventDestroy(evA);
    cudaEventDestroy(evQ);
    cudaEventDestroy(evJ1);
    cudaEventDestroy(evJ2);
    cudaStreamDestroy(s1);
    cudaStreamDestroy(s2);
}

// round 15
// speedup vs baseline: 2.5781x; 1.4726x over previous
#include <cuda_runtime.h>
#include <cuda_fp16.h>
#include <cstdint>
#include <math.h>

// ---------------------------------------------------------------------------
// Problem constants
// ---------------------------------------------------------------------------
#define B_   16
#define LP_  1024
#define LD_  256
#define DP_  1280
#define DE_  512
#define LC_  256

#define MPR  (B_ * LP_)      // 16384
#define MDR  (B_ * LD_)      // 4096

// ---------------------------------------------------------------------------
// Helpers
// ---------------------------------------------------------------------------
__device__ __forceinline__ uint32_t smem_u32(const void* p) {
    uint32_t a;
    asm("{ .reg .u64 t; cvta.to.shared.u64 t, %1; cvt.u32.u64 %0, t; }"
        : "=r"(a) : "l"(p));
    return a;
}

__device__ __forceinline__ void cpa16(uint32_t saddr, const void* g) {
    asm volatile("cp.async.cg.shared.global [%0], [%1], 16;"
                 :: "r"(saddr), "l"(g) : "memory");
}
#define CP_COMMIT() asm volatile("cp.async.commit_group;" ::: "memory")
#define CP_WAIT0()  asm volatile("cp.async.wait_group 0;" ::: "memory")
#define CP_WAIT1()  asm volatile("cp.async.wait_group 1;" ::: "memory")

#define LDSM4(r, addr) \
    asm volatile("ldmatrix.sync.aligned.m8n8.x4.shared.b16 {%0,%1,%2,%3}, [%4];" \
        : "=r"((r)[0]), "=r"((r)[1]), "=r"((r)[2]), "=r"((r)[3]) : "r"(addr))

#define MMA16816(d, a, b) \
    asm volatile("mma.sync.aligned.m16n8k16.row.col.f32.f16.f16.f32 " \
        "{%0,%1,%2,%3}, {%4,%5,%6,%7}, {%8,%9}, {%0,%1,%2,%3};" \
        : "+f"((d)[0]), "+f"((d)[1]), "+f"((d)[2]), "+f"((d)[3]) \
        : "r"((a)[0]), "r"((a)[1]), "r"((a)[2]), "r"((a)[3]), \
          "r"((b)[0]), "r"((b)[1]))

// ---------------------------------------------------------------------------
// Scratch (fp16; hl buffers: hi at [0,sz), lo at [sz,2sz)); 16B aligned
// ---------------------------------------------------------------------------
__device__ __align__(16) __half g_prf   [(size_t)MPR * DP_];      // hi only
__device__ __align__(16) __half g_drugf [(size_t)MDR * DE_];      // hi only
__device__ __align__(16) __half g_prconf[2ull * LC_ * DP_];
__device__ __align__(16) __half g_drconf[2ull * LC_ * DE_];
__device__ __align__(16) __half g_Wqhl  [2ull * DP_ * DP_];
__device__ __align__(16) __half g_WkT   [2ull * DP_ * DP_];
__device__ __align__(16) __half g_Wq2hl [2ull * DE_ * DE_];
__device__ __align__(16) __half g_Wk2T  [2ull * DE_ * DE_];
__device__ __align__(16) __half g_WprTt [2ull * DE_ * DP_];
__device__ __align__(16) __half g_WprTb [2ull * DE_ * DP_];

__device__ __align__(16) float  g_Kpr   [(size_t)LC_ * DP_];
__device__ __align__(16) __half g_Kprhl [2ull * LC_ * DP_];
__device__ __align__(16) __half g_P1Thl [2ull * LC_ * DP_];
__device__ __align__(16) __half g_P2Thl [2ull * DE_ * LC_];
__device__ __align__(16) float  g_att   [(size_t)MPR * LC_];
__device__ __align__(16) __half g_atthl [(size_t)MPR * LC_];      // hi only
__device__ __align__(16) float  g_bqrow [LC_];

__device__ __align__(16) float  g_Kdr   [(size_t)LC_ * DE_];
__device__ __align__(16) __half g_Kdrhl [2ull * LC_ * DE_];
__device__ __align__(16) __half g_KdrT  [2ull * DE_ * LC_];
__device__ __align__(16) __half g_P1dThl[2ull * LC_ * DE_];
__device__ __align__(16) float  g_attdr [(size_t)MDR * LC_];
__device__ __align__(16) __half g_attdrhl[(size_t)MDR * LC_];     // hi only
__device__ __align__(16) float  g_bq2row[LC_];

// ---------------------------------------------------------------------------
// mma.sync fp16 GEMM: C = alpha * A*B^T (+bias), hi/lo split accumulation.
// nC=3: (Ah,Bh),(Ah,Bl),(Al,Bh)   nC=2: (Ah,Bh),(Ah,Bl)   nC=1: (Ah,Bh)
// A:[M,K], B:[N,K] row-major fp16. Tile 128x128, K-stage 32, double-buffered.
// (R7 core — proven fastest config; do not touch.)
// ---------------------------------------------------------------------------
#define STG 10240
#define ROWB 80

__global__ __launch_bounds__(256) void gemm_mma(
    const __half* __restrict__ A, size_t aLo,
    const __half* __restrict__ Bm, size_t bLo,
    int K, int nC,
    float* __restrict__ outF, int accumF, int ldcF,
    __half* __restrict__ outH, size_t outLoH, int ldcH,
    const float* __restrict__ bias, float alpha)
{
    __shared__ __align__(16) char smem[4 * STG];
    const uint32_t sA = smem_u32(smem);
    const uint32_t sB = sA + 2 * STG;

    const int tid = threadIdx.x;
    const int lane = tid & 31;
    const int warp = tid >> 5;
    const int m0 = blockIdx.y * 128;
    const int n0 = blockIdx.x * 128;
    const int wm = (warp & 1) * 64;
    const int wn = (warp >> 1) * 32;

    const __half* Ap[3] = {A, A, A + aLo};
    const __half* Bp[3] = {Bm, Bm + bLo, Bm};

    const int Ks = K >> 5;
    const int total = nC * Ks;

    const int lr0 = tid >> 2;
    const int lc0 = (tid & 3) * 16;

    const int arow = lane & 15;
    const int acol = (lane >> 4) * 16;
    uint32_t aBase[4];
    #pragma unroll
    for (int i = 0; i < 4; i++)
        aBase[i] = sA + (wm + 16 * i + arow) * ROWB + acol;
    const int brow = (lane & 7) + ((lane >> 4) & 1) * 8;
    const int bcol = ((lane >> 3) & 1) * 16;
    uint32_t bBase[2];
    #pragma unroll
    for (int j = 0; j < 2; j++)
        bBase[j] = sB + (wn + 16 * j + brow) * ROWB + bcol;

    float acc[4][4][4];
    #pragma unroll
    for (int i = 0; i < 4; i++)
        #pragma unroll
        for (int j = 0; j < 4; j++)
            #pragma unroll
            for (int e = 0; e < 4; e++) acc[i][j][e] = 0.0f;

    auto load_stage = [&](int s) {
        const int p = s / Ks;
        const int t = s - p * Ks;
        const int buf = s & 1;
        const char* Ag = (const char*)Ap[p];
        const char* Bg = (const char*)Bp[p];
        const size_t kb = (size_t)t * 64;
        #pragma unroll
        for (int h = 0; h < 2; h++) {
            const int row = lr0 + h * 64;
            const uint32_t sa = buf * STG + row * ROWB + lc0;
            cpa16(sA + sa, Ag + ((size_t)(m0 + row) * K) * 2 + kb + lc0);
            cpa16(sB + sa, Bg + ((size_t)(n0 + row) * K) * 2 + kb + lc0);
        }
        CP_COMMIT();
    };

    load_stage(0);
    load_stage(1);

    for (int s = 0; s < total; s++) {
        if (s + 1 < total) { CP_WAIT1(); } else { CP_WAIT0(); }
        __syncthreads();

        const int buf = s & 1;
        const uint32_t off = buf * STG;
        #pragma unroll
        for (int kstep = 0; kstep < 2; kstep++) {
            uint32_t aF[4][4], bF[2][4];
            #pragma unroll
            for (int i = 0; i < 4; i++)
                LDSM4(aF[i], aBase[i] + off + kstep * 32);
            #pragma unroll
            for (int j = 0; j < 2; j++)
                LDSM4(bF[j], bBase[j] + off + kstep * 32);
            #pragma unroll
            for (int i = 0; i < 4; i++)
                #pragma unroll
                for (int j = 0; j < 4; j++) {
                    uint32_t bb[2] = {bF[j >> 1][(j & 1) * 2],
                                      bF[j >> 1][(j & 1) * 2 + 1]};
                    MMA16816(acc[i][j], aF[i], bb);
                }
        }
        __syncthreads();
        if (s + 2 < total) load_stage(s + 2);
    }

    const int mrow = m0 + wm + (lane >> 2);
    const int ncb  = n0 + wn + 2 * (lane & 3);

    #pragma unroll
    for (int j = 0; j < 4; j++) {
        const int n = ncb + 8 * j;
        float badd0 = 0.0f, badd1 = 0.0f;
        if (bias) { badd0 = bias[n]; badd1 = bias[n + 1]; }
        #pragma unroll
        for (int i = 0; i < 4; i++) {
            #pragma unroll
            for (int half_ = 0; half_ < 2; half_++) {
                const int m = mrow + 16 * i + 8 * half_;
                float v0 = acc[i][j][2 * half_ + 0] * alpha + badd0;
                float v1 = acc[i][j][2 * half_ + 1] * alpha + badd1;
                if (outH) {
                    const size_t base = (size_t)m * ldcH + n;
                    const __half h0 = __float2half(v0);
                    const __half h1 = __float2half(v1);
                    const __half l0 = __float2half(v0 - __half2float(h0));
                    const __half l1 = __float2half(v1 - __half2float(h1));
                    *(__half2*)&outH[base] = __halves2half2(h0, h1);
                    *(__half2*)&outH[base + outLoH] = __halves2half2(l0, l1);
                }
                if (outF) {
                    const size_t base = (size_t)m * ldcF + n;
                    if (accumF) {
                        float2 o = *(float2*)&outF[base];
                        v0 += o.x; v1 += o.y;
                    }
                    float2 w; w.x = v0; w.y = v1;
                    *(float2*)&outF[base] = w;
                }
            }
        }
    }
}

// ---------------------------------------------------------------------------
// fp32 -> fp16 hi/lo split
// ---------------------------------------------------------------------------
__global__ __launch_bounds__(256) void split_k(
    const float* __restrict__ in, __half* __restrict__ oh,
    size_t loOff, int n4)
{
    const int i = blockIdx.x * blockDim.x + threadIdx.x;
    if (i >= n4) return;
    const float4 v = ((const float4*)in)[i];
    const float vv[4] = {v.x, v.y, v.z, v.w};
    __half h[4], l[4];
    #pragma unroll
    for (int j = 0; j < 4; j++) {
        h[j] = __float2half(vv[j]);
        l[j] = __float2half(vv[j] - __half2float(h[j]));
    }
    *(uint2*)&oh[(size_t)i * 4]         = *(uint2*)h;
    *(uint2*)&oh[loOff + (size_t)i * 4] = *(uint2*)l;
}

// fp32 -> fp16 hi only
__global__ __launch_bounds__(256) void split_h(
    const float* __restrict__ in, __half* __restrict__ oh, int n4)
{
    const int i = blockIdx.x * blockDim.x + threadIdx.x;
    if (i >= n4) return;
    const float4 v = ((const float4*)in)[i];
    __half h[4];
    h[0] = __float2half(v.x); h[1] = __float2half(v.y);
    h[2] = __float2half(v.z); h[3] = __float2half(v.w);
    *(uint2*)&oh[(size_t)i * 4] = *(uint2*)h;
}

// ---------------------------------------------------------------------------
// fp32 [R,C] -> transposed fp16 hi/lo [C,R]
// ---------------------------------------------------------------------------
__global__ __launch_bounds__(256) void tsplit_k(
    const float* __restrict__ in, int R, int C,
    __half* __restrict__ oh, size_t loOff)
{
    __shared__ float t[32][33];
    const int c0 = blockIdx.x * 32;
    const int rr0 = blockIdx.y * 32;
    const int tx = threadIdx.x;
    const int ty = threadIdx.y;
    #pragma unroll
    for (int i = 0; i < 4; i++)
        t[ty + 8 * i][tx] = in[(size_t)(rr0 + ty + 8 * i) * C + c0 + tx];
    __syncthreads();
    #pragma unroll
    for (int i = 0; i < 4; i++) {
        const float v = t[tx][ty + 8 * i];
        const __half hh = __float2half(v);
        const __half ll = __float2half(v - __half2float(hh));
        const size_t o = (size_t)(c0 + ty + 8 * i) * R + rr0 + tx;
        oh[o] = hh;
        oh[loOff + o] = ll;
    }
}

// ---------------------------------------------------------------------------
// out[c] = alpha * dot(bvec, Kmat[c,:])
// ---------------------------------------------------------------------------
__global__ __launch_bounds__(256) void bias_row_k(
    const float* __restrict__ bvec, const float* __restrict__ Kmat,
    int K, float alpha, float* __restrict__ outv)
{
    const int c = blockIdx.x;
    const int tid = threadIdx.x;
    float s = 0.0f;
    for (int k = tid; k < K; k += 256)
        s += bvec[k] * Kmat[(size_t)c * K + k];
    __shared__ float red[8];
    const int lane = tid & 31;
    const int warp = tid >> 5;
    #pragma unroll
    for (int o = 16; o > 0; o >>= 1)
        s += __shfl_xor_sync(0xffffffffu, s, o);
    if (lane == 0) red[warp] = s;
    __syncthreads();
    if (tid == 0) {
        float t = 0.0f;
        #pragma unroll
        for (int i = 0; i < 8; i++) t += red[i];
        outv[c] = t * alpha;
    }
}

// ---------------------------------------------------------------------------
// Masked softmax (LC=256 cols) -> fp16 hi
// ---------------------------------------------------------------------------
__global__ __launch_bounds__(256) void softmax_split_k(
    const float* __restrict__ att, const int* __restrict__ mask,
    __half* __restrict__ oh)
{
    const int row = blockIdx.x;
    const int c = threadIdx.x;
    const size_t idx = (size_t)row * LC_ + c;

    float v = att[idx];
    if (mask[row] != 0) v = -1e10f;

    __shared__ float red_max[8];
    __shared__ float red_sum[8];
    const int lane = c & 31;
    const int warp = c >> 5;

    float m = v;
    #pragma unroll
    for (int o = 16; o > 0; o >>= 1)
        m = fmaxf(m, __shfl_xor_sync(0xffffffffu, m, o));
    if (lane == 0) red_max[warp] = m;
    __syncthreads();
    float mmax = red_max[0];
    #pragma unroll
    for (int i = 1; i < 8; i++) mmax = fmaxf(mmax, red_max[i]);

    const float e = expf(v - mmax);

    float s = e;
    #pragma unroll
    for (int o = 16; o > 0; o >>= 1)
        s += __shfl_xor_sync(0xffffffffu, s, o);
    if (lane == 0) red_sum[warp] = s;
    __syncthreads();
    float ssum = red_sum[0];
    #pragma unroll
    for (int i = 1; i < 8; i++) ssum += red_sum[i];

    oh[idx] = __float2half(e / ssum);
}

// ---------------------------------------------------------------------------
// Copy drug_f into first half of drug output rows
// ---------------------------------------------------------------------------
__global__ __launch_bounds__(256) void copy_drug_kernel(
    const float* __restrict__ drug_f, float* __restrict__ out)
{
    const int idx = blockIdx.x * blockDim.x + threadIdx.x;
    if (idx >= MDR * (DE_ / 4)) return;
    const int m = idx / (DE_ / 4);
    const int n4 = idx % (DE_ / 4);
    const float4 v = ((const float4*)drug_f)[(size_t)m * (DE_ / 4) + n4];
    ((float4*)out)[(size_t)m * (2 * DE_ / 4) + n4] = v;
}

// ---------------------------------------------------------------------------
// Launch — forked multi-stream graph
// ---------------------------------------------------------------------------
static inline void* sym(const void* s) {
    void* p = 0;
    cudaGetSymbolAddress(&p, s);
    return p;
}

extern "C" void kernel_launch(void* const* d_in, const int* in_sizes, int n_in,
                              void* d_out, int out_size)
{
    const float* pr_f    = (const float*)d_in[0];
    const float* drug_f  = (const float*)d_in[1];
    const float* pr_conf = (const float*)d_in[2];
    const float* dr_conf = (const float*)d_in[3];
    const float* Wq  = (const float*)d_in[4];
    const float* bq  = (const float*)d_in[5];
    const float* Wk  = (const float*)d_in[6];
    const float* bk  = (const float*)d_in[7];
    const float* Wq2 = (const float*)d_in[8];
    const float* bq2 = (const float*)d_in[9];
    const float* Wk2 = (const float*)d_in[10];
    const float* bk2 = (const float*)d_in[11];
    const float* Wpr = (const float*)d_in[12];
    const float* bpr = (const float*)d_in[13];
    const int* pmask = (const int*)d_in[14];
    const int* dmask = (const int*)d_in[15];

    float* out    = (float*)d_out;
    float* pr_out = out;                                  // [16384, 512]
    float* dr_out = out + (size_t)MPR * DE_;              // [4096, 1024]

    __half* prf    = (__half*)sym(g_prf);
    __half* drugf  = (__half*)sym(g_drugf);
    __half* prconf = (__half*)sym(g_prconf);
    __half* drconf = (__half*)sym(g_drconf);
    __half* Wqhl   = (__half*)sym(g_Wqhl);
    __half* WkT    = (__half*)sym(g_WkT);
    __half* Wq2hl  = (__half*)sym(g_Wq2hl);
    __half* Wk2T   = (__half*)sym(g_Wk2T);
    __half* WprTt  = (__half*)sym(g_WprTt);
    __half* WprTb  = (__half*)sym(g_WprTb);
    float*  Kpr    = (float*)sym(g_Kpr);
    __half* Kprhl  = (__half*)sym(g_Kprhl);
    __half* P1Thl  = (__half*)sym(g_P1Thl);
    __half* P2Thl  = (__half*)sym(g_P2Thl);
    float*  att    = (float*)sym(g_att);
    __half* atthl  = (__half*)sym(g_atthl);
    float*  bqrow  = (float*)sym(g_bqrow);
    float*  Kdr    = (float*)sym(g_Kdr);
    __half* Kdrhl  = (__half*)sym(g_Kdrhl);
    __half* KdrT   = (__half*)sym(g_KdrT);
    __half* P1dThl = (__half*)sym(g_P1dThl);
    float*  attdr  = (float*)sym(g_attdr);
    __half* attdrhl= (__half*)sym(g_attdrhl);
    float*  bq2row = (float*)sym(g_bq2row);

    const float pr_alpha = 1.0f / 16.0f;
    const float dr_alpha = 1.0f / sqrtf((float)DE_);

    cudaStream_t s1, s2;
    cudaStreamCreateWithFlags(&s1, cudaStreamNonBlocking);
    cudaStreamCreateWithFlags(&s2, cudaStreamNonBlocking);
    cudaEvent_t evStart, evA, evQ, evJ1, evJ2, evK, evWq, evWb, evP2;
    cudaEventCreateWithFlags(&evStart, cudaEventDisableTiming);
    cudaEventCreateWithFlags(&evA, cudaEventDisableTiming);
    cudaEventCreateWithFlags(&evQ, cudaEventDisableTiming);
    cudaEventCreateWithFlags(&evJ1, cudaEventDisableTiming);
    cudaEventCreateWithFlags(&evJ2, cudaEventDisableTiming);
    cudaEventCreateWithFlags(&evK, cudaEventDisableTiming);
    cudaEventCreateWithFlags(&evWq, cudaEventDisableTiming);
    cudaEventCreateWithFlags(&evWb, cudaEventDisableTiming);
    cudaEventCreateWithFlags(&evP2, cudaEventDisableTiming);

    cudaEventRecord(evStart, 0);
    cudaStreamWaitEvent(s1, evStart, 0);
    cudaStreamWaitEvent(s2, evStart, 0);

    // ======== stream s1: pr_f hi-split, Wq/WprTb prep, prout1 ========
    {
        const int n4 = MPR * DP_ / 4;
        split_h<<<(n4 + 255) / 256, 256, 0, s1>>>(pr_f, prf, n4);
        cudaEventRecord(evA, s1);     // prf ready
        {
            const int w4 = DP_ * DP_ / 4;
            split_k<<<(w4 + 255) / 256, 256, 0, s1>>>(Wq, Wqhl, (size_t)DP_ * DP_, w4);
        }
        cudaEventRecord(evWq, s1);    // Wqhl ready (for P1T on stream 0)
        tsplit_k<<<dim3(DE_ / 32, DP_ / 32), dim3(32, 8), 0, s1>>>(
            Wpr + (size_t)DP_ * DE_, DP_, DE_, WprTb, (size_t)DE_ * DP_);
        cudaEventRecord(evWb, s1);    // WprTb ready (for P2T on s2)
        tsplit_k<<<dim3(DE_ / 32, DP_ / 32), dim3(32, 8), 0, s1>>>(
            Wpr, DP_, DE_, WprTt, (size_t)DE_ * DP_);
        // prout1 = pr_f @ WprTop + bpr   (1-combo hi*hi)
        gemm_mma<<<dim3(DE_ / 128, MPR / 128), 256, 0, s1>>>(
            prf, 0, WprTt, (size_t)DE_ * DP_, DP_, 1,
            pr_out, 0, DE_, (__half*)0, 0, 0, bpr, 1.0f);
        cudaEventRecord(evQ, s1);     // pr_out base ready
        copy_drug_kernel<<<(MDR * (DE_ / 4) + 255) / 256, 256, 0, s1>>>(drug_f, dr_out);
        cudaEventRecord(evJ1, s1);
    }

    // ======== stream s2: entire drug path, then P2T ========
    {
        int n4 = MDR * DE_ / 4;
        split_h<<<(n4 + 255) / 256, 256, 0, s2>>>(drug_f, drugf, n4);
        n4 = LC_ * DE_ / 4;
        split_k<<<(n4 + 255) / 256, 256, 0, s2>>>(dr_conf, drconf, (size_t)LC_ * DE_, n4);
        n4 = DE_ * DE_ / 4;
        split_k<<<(n4 + 255) / 256, 256, 0, s2>>>(Wq2, Wq2hl, (size_t)DE_ * DE_, n4);
        tsplit_k<<<dim3(DE_ / 32, DE_ / 32), dim3(32, 8), 0, s2>>>(
            Wk2, DE_, DE_, Wk2T, (size_t)DE_ * DE_);
        // Kdr = dr_conf @ Wk2 + bk2 (3-combo; f32 + hi/lo out)
        gemm_mma<<<dim3(DE_ / 128, LC_ / 128), 256, 0, s2>>>(
            drconf, (size_t)LC_ * DE_, Wk2T, (size_t)DE_ * DE_, DE_, 3,
            Kdr, 0, DE_, Kdrhl, (size_t)LC_ * DE_, DE_, bk2, 1.0f);
        tsplit_k<<<dim3(DE_ / 32, LC_ / 32), dim3(32, 8), 0, s2>>>(
            Kdr, LC_, DE_, KdrT, (size_t)DE_ * LC_);
        // P1dT = Kdr @ Wq2^T (2-combo; hi/lo only — consumer reads hi only)
        gemm_mma<<<dim3(DE_ / 128, LC_ / 128), 256, 0, s2>>>(
            Kdrhl, (size_t)LC_ * DE_, Wq2hl, (size_t)DE_ * DE_, DE_, 2,
            (float*)0, 0, 0, P1dThl, (size_t)LC_ * DE_, DE_, (const float*)0, 1.0f);
        bias_row_k<<<LC_, 256, 0, s2>>>(bq2, Kdr, DE_, dr_alpha, bq2row);
        // att_dr = drug_f @ P1dT^T * dr_alpha + bq2row   (1-combo)
        gemm_mma<<<dim3(LC_ / 128, MDR / 128), 256, 0, s2>>>(
            drugf, 0, P1dThl, (size_t)LC_ * DE_, DE_, 1,
            attdr, 0, LC_, (__half*)0, 0, 0, bq2row, dr_alpha);
        softmax_split_k<<<MDR, 256, 0, s2>>>(attdr, dmask, attdrhl);
        // dr_out[:, 512:] = S_dr @ Kdr   (1-combo)
        gemm_mma<<<dim3(DE_ / 128, MDR / 128), 256, 0, s2>>>(
            attdrhl, 0, KdrT, (size_t)DE_ * LC_, LC_, 1,
            dr_out + DE_, 0, 2 * DE_, (__half*)0, 0, 0, (const float*)0, 1.0f);
        cudaEventRecord(evJ2, s2);
        // P2T = WprBot contracted with Kpr (2-combo; off critical path)
        cudaStreamWaitEvent(s2, evK, 0);
        cudaStreamWaitEvent(s2, evWb, 0);
        gemm_mma<<<dim3(LC_ / 128, DE_ / 128), 256, 0, s2>>>(
            WprTb, (size_t)DE_ * DP_, Kprhl, (size_t)LC_ * DP_, DP_, 2,
            (float*)0, 0, 0, P2Thl, (size_t)DE_ * LC_, LC_, (const float*)0, 1.0f);
        cudaEventRecord(evP2, s2);
    }

    // ======== stream 0: protein attention chain ========
    {
        int n4 = LC_ * DP_ / 4;
        split_k<<<(n4 + 255) / 256, 256>>>(pr_conf, prconf, (size_t)LC_ * DP_, n4);
        tsplit_k<<<dim3(DP_ / 32, DP_ / 32), dim3(32, 8)>>>(
            Wk, DP_, DP_, WkT, (size_t)DP_ * DP_);
        // Kpr = pr_conf @ Wk + bk (3-combo; f32 + hi/lo)
        gemm_mma<<<dim3(DP_ / 128, LC_ / 128), 256>>>(
            prconf, (size_t)LC_ * DP_, WkT, (size_t)DP_ * DP_, DP_, 3,
            Kpr, 0, DP_, Kprhl, (size_t)LC_ * DP_, DP_, bk, 1.0f);
        cudaEventRecord(evK, 0);      // Kprhl ready (for P2T on s2)
        bias_row_k<<<LC_, 256>>>(bq, Kpr, DP_, pr_alpha, bqrow);
        // P1T = Kpr @ Wq^T (2-combo; consumer att reads hi only)
        cudaStreamWaitEvent(0, evWq, 0);
        gemm_mma<<<dim3(DP_ / 128, LC_ / 128), 256>>>(
            Kprhl, (size_t)LC_ * DP_, Wqhl, (size_t)DP_ * DP_, DP_, 2,
            (float*)0, 0, 0, P1Thl, (size_t)LC_ * DP_, DP_, (const float*)0, 1.0f);
        // att = pr_f @ P1T^T / 16 + bqrow  (1-combo; needs prf from s1)
        cudaStreamWaitEvent(0, evA, 0);
        gemm_mma<<<dim3(LC_ / 128, MPR / 128), 256>>>(
            prf, 0, P1Thl, (size_t)LC_ * DP_, DP_, 1,
            att, 0, LC_, (__half*)0, 0, 0, bqrow, pr_alpha);
        softmax_split_k<<<MPR, 256>>>(att, pmask, atthl);
        // pr_out += S @ P2T^T  (1-combo; needs prout1 + P2T)
        cudaStreamWaitEvent(0, evQ, 0);
        cudaStreamWaitEvent(0, evP2, 0);
        gemm_mma<<<dim3(DE_ / 128, MPR / 128), 256>>>(
            atthl, 0, P2Thl, (size_t)DE_ * LC_, LC_, 1,
            pr_out, 1, DE_, (__half*)0, 0, 0, (const float*)0, 1.0f);
    }

    cudaStreamWaitEvent(0, evJ1, 0);
    cudaStreamWaitEvent(0, evJ2, 0);

    cudaEventDestroy(evStart);
    cudaEventDestroy(evA);
    cudaEventDestroy(evQ);
    cudaEventDestroy(evJ1);
    cudaEventDestroy(evJ2);
    cudaEventDestroy(evK);
    cudaEventDestroy(evWq);
    cudaEventDestroy(evWb);
    cudaEventDestroy(evP2);
    cudaStreamDestroy(s1);
    cudaStreamDestroy(s2);
}

// round 16
// speedup vs baseline: 2.7738x; 1.0759x over previous
#include <cuda_runtime.h>
#include <cuda_fp16.h>
#include <cstdint>
#include <math.h>

// ---------------------------------------------------------------------------
// Problem constants
// ---------------------------------------------------------------------------
#define B_   16
#define LP_  1024
#define LD_  256
#define DP_  1280
#define DE_  512
#define LC_  256

#define MPR  (B_ * LP_)      // 16384
#define MDR  (B_ * LD_)      // 4096

// ---------------------------------------------------------------------------
// Helpers
// ---------------------------------------------------------------------------
__device__ __forceinline__ uint32_t smem_u32(const void* p) {
    uint32_t a;
    asm("{ .reg .u64 t; cvta.to.shared.u64 t, %1; cvt.u32.u64 %0, t; }"
        : "=r"(a) : "l"(p));
    return a;
}

__device__ __forceinline__ void cpa16(uint32_t saddr, const void* g) {
    asm volatile("cp.async.cg.shared.global [%0], [%1], 16;"
                 :: "r"(saddr), "l"(g) : "memory");
}
#define CP_COMMIT() asm volatile("cp.async.commit_group;" ::: "memory")
#define CP_WAIT0()  asm volatile("cp.async.wait_group 0;" ::: "memory")
#define CP_WAIT1()  asm volatile("cp.async.wait_group 1;" ::: "memory")

#define LDSM4(r, addr) \
    asm volatile("ldmatrix.sync.aligned.m8n8.x4.shared.b16 {%0,%1,%2,%3}, [%4];" \
        : "=r"((r)[0]), "=r"((r)[1]), "=r"((r)[2]), "=r"((r)[3]) : "r"(addr))

#define MMA16816(d, a, b) \
    asm volatile("mma.sync.aligned.m16n8k16.row.col.f32.f16.f16.f32 " \
        "{%0,%1,%2,%3}, {%4,%5,%6,%7}, {%8,%9}, {%0,%1,%2,%3};" \
        : "+f"((d)[0]), "+f"((d)[1]), "+f"((d)[2]), "+f"((d)[3]) \
        : "r"((a)[0]), "r"((a)[1]), "r"((a)[2]), "r"((a)[3]), \
          "r"((b)[0]), "r"((b)[1]))

// ---------------------------------------------------------------------------
// Scratch (fp16; hl buffers: hi at [0,sz), lo at [sz,2sz)); 16B aligned
// ---------------------------------------------------------------------------
__device__ __align__(16) __half g_prf   [(size_t)MPR * DP_];      // hi only
__device__ __align__(16) __half g_drugf [(size_t)MDR * DE_];      // hi only
__device__ __align__(16) __half g_prconf[2ull * LC_ * DP_];
__device__ __align__(16) __half g_drconf[2ull * LC_ * DE_];
__device__ __align__(16) __half g_Wqhl  [2ull * DP_ * DP_];
__device__ __align__(16) __half g_WkT   [2ull * DP_ * DP_];
__device__ __align__(16) __half g_Wq2hl [2ull * DE_ * DE_];
__device__ __align__(16) __half g_Wk2T  [2ull * DE_ * DE_];
__device__ __align__(16) __half g_WprTt [2ull * DE_ * DP_];
__device__ __align__(16) __half g_WprTb [2ull * DE_ * DP_];

__device__ __align__(16) float  g_Kpr   [(size_t)LC_ * DP_];
__device__ __align__(16) __half g_Kprhl [2ull * LC_ * DP_];
__device__ __align__(16) __half g_P1Thl [2ull * LC_ * DP_];
__device__ __align__(16) __half g_P2Thl [2ull * DE_ * LC_];
__device__ __align__(16) float  g_att   [(size_t)MPR * LC_];
__device__ __align__(16) __half g_atthl [(size_t)MPR * LC_];      // hi only
__device__ __align__(16) float  g_bqrow [LC_];
__device__ __align__(16) float  g_tmpO  [(size_t)MPR * DE_];      // S@P2T partial

__device__ __align__(16) float  g_Kdr   [(size_t)LC_ * DE_];
__device__ __align__(16) __half g_Kdrhl [2ull * LC_ * DE_];
__device__ __align__(16) __half g_KdrT  [2ull * DE_ * LC_];
__device__ __align__(16) __half g_P1dThl[2ull * LC_ * DE_];
__device__ __align__(16) float  g_attdr [(size_t)MDR * LC_];
__device__ __align__(16) __half g_attdrhl[(size_t)MDR * LC_];     // hi only
__device__ __align__(16) float  g_bq2row[LC_];

// ---------------------------------------------------------------------------
// mma.sync fp16 GEMM: C = alpha * A*B^T (+bias), hi/lo split accumulation.
// nC=3: (Ah,Bh),(Ah,Bl),(Al,Bh)   nC=2: (Ah,Bh),(Ah,Bl)   nC=1: (Ah,Bh)
// A:[M,K], B:[N,K] row-major fp16. Tile 128x128, K-stage 32, double-buffered.
// (R7 core — proven fastest config; do not touch.)
// ---------------------------------------------------------------------------
#define STG 10240
#define ROWB 80

__global__ __launch_bounds__(256) void gemm_mma(
    const __half* __restrict__ A, size_t aLo,
    const __half* __restrict__ Bm, size_t bLo,
    int K, int nC,
    float* __restrict__ outF, int accumF, int ldcF,
    __half* __restrict__ outH, size_t outLoH, int ldcH,
    const float* __restrict__ bias, float alpha)
{
    __shared__ __align__(16) char smem[4 * STG];
    const uint32_t sA = smem_u32(smem);
    const uint32_t sB = sA + 2 * STG;

    const int tid = threadIdx.x;
    const int lane = tid & 31;
    const int warp = tid >> 5;
    const int m0 = blockIdx.y * 128;
    const int n0 = blockIdx.x * 128;
    const int wm = (warp & 1) * 64;
    const int wn = (warp >> 1) * 32;

    const __half* Ap[3] = {A, A, A + aLo};
    const __half* Bp[3] = {Bm, Bm + bLo, Bm};

    const int Ks = K >> 5;
    const int total = nC * Ks;

    const int lr0 = tid >> 2;
    const int lc0 = (tid & 3) * 16;

    const int arow = lane & 15;
    const int acol = (lane >> 4) * 16;
    uint32_t aBase[4];
    #pragma unroll
    for (int i = 0; i < 4; i++)
        aBase[i] = sA + (wm + 16 * i + arow) * ROWB + acol;
    const int brow = (lane & 7) + ((lane >> 4) & 1) * 8;
    const int bcol = ((lane >> 3) & 1) * 16;
    uint32_t bBase[2];
    #pragma unroll
    for (int j = 0; j < 2; j++)
        bBase[j] = sB + (wn + 16 * j + brow) * ROWB + bcol;

    float acc[4][4][4];
    #pragma unroll
    for (int i = 0; i < 4; i++)
        #pragma unroll
        for (int j = 0; j < 4; j++)
            #pragma unroll
            for (int e = 0; e < 4; e++) acc[i][j][e] = 0.0f;

    auto load_stage = [&](int s) {
        const int p = s / Ks;
        const int t = s - p * Ks;
        const int buf = s & 1;
        const char* Ag = (const char*)Ap[p];
        const char* Bg = (const char*)Bp[p];
        const size_t kb = (size_t)t * 64;
        #pragma unroll
        for (int h = 0; h < 2; h++) {
            const int row = lr0 + h * 64;
            const uint32_t sa = buf * STG + row * ROWB + lc0;
            cpa16(sA + sa, Ag + ((size_t)(m0 + row) * K) * 2 + kb + lc0);
            cpa16(sB + sa, Bg + ((size_t)(n0 + row) * K) * 2 + kb + lc0);
        }
        CP_COMMIT();
    };

    load_stage(0);
    load_stage(1);

    for (int s = 0; s < total; s++) {
        if (s + 1 < total) { CP_WAIT1(); } else { CP_WAIT0(); }
        __syncthreads();

        const int buf = s & 1;
        const uint32_t off = buf * STG;
        #pragma unroll
        for (int kstep = 0; kstep < 2; kstep++) {
            uint32_t aF[4][4], bF[2][4];
            #pragma unroll
            for (int i = 0; i < 4; i++)
                LDSM4(aF[i], aBase[i] + off + kstep * 32);
            #pragma unroll
            for (int j = 0; j < 2; j++)
                LDSM4(bF[j], bBase[j] + off + kstep * 32);
            #pragma unroll
            for (int i = 0; i < 4; i++)
                #pragma unroll
                for (int j = 0; j < 4; j++) {
                    uint32_t bb[2] = {bF[j >> 1][(j & 1) * 2],
                                      bF[j >> 1][(j & 1) * 2 + 1]};
                    MMA16816(acc[i][j], aF[i], bb);
                }
        }
        __syncthreads();
        if (s + 2 < total) load_stage(s + 2);
    }

    const int mrow = m0 + wm + (lane >> 2);
    const int ncb  = n0 + wn + 2 * (lane & 3);

    #pragma unroll
    for (int j = 0; j < 4; j++) {
        const int n = ncb + 8 * j;
        float badd0 = 0.0f, badd1 = 0.0f;
        if (bias) { badd0 = bias[n]; badd1 = bias[n + 1]; }
        #pragma unroll
        for (int i = 0; i < 4; i++) {
            #pragma unroll
            for (int half_ = 0; half_ < 2; half_++) {
                const int m = mrow + 16 * i + 8 * half_;
                float v0 = acc[i][j][2 * half_ + 0] * alpha + badd0;
                float v1 = acc[i][j][2 * half_ + 1] * alpha + badd1;
                if (outH) {
                    const size_t base = (size_t)m * ldcH + n;
                    const __half h0 = __float2half(v0);
                    const __half h1 = __float2half(v1);
                    const __half l0 = __float2half(v0 - __half2float(h0));
                    const __half l1 = __float2half(v1 - __half2float(h1));
                    *(__half2*)&outH[base] = __halves2half2(h0, h1);
                    *(__half2*)&outH[base + outLoH] = __halves2half2(l0, l1);
                }
                if (outF) {
                    const size_t base = (size_t)m * ldcF + n;
                    if (accumF) {
                        float2 o = *(float2*)&outF[base];
                        v0 += o.x; v1 += o.y;
                    }
                    float2 w; w.x = v0; w.y = v1;
                    *(float2*)&outF[base] = w;
                }
            }
        }
    }
}

// ---------------------------------------------------------------------------
// fp32 -> fp16 hi/lo split
// ---------------------------------------------------------------------------
__global__ __launch_bounds__(256) void split_k(
    const float* __restrict__ in, __half* __restrict__ oh,
    size_t loOff, int n4)
{
    const int i = blockIdx.x * blockDim.x + threadIdx.x;
    if (i >= n4) return;
    const float4 v = ((const float4*)in)[i];
    const float vv[4] = {v.x, v.y, v.z, v.w};
    __half h[4], l[4];
    #pragma unroll
    for (int j = 0; j < 4; j++) {
        h[j] = __float2half(vv[j]);
        l[j] = __float2half(vv[j] - __half2float(h[j]));
    }
    *(uint2*)&oh[(size_t)i * 4]         = *(uint2*)h;
    *(uint2*)&oh[loOff + (size_t)i * 4] = *(uint2*)l;
}

// fp32 -> fp16 hi only
__global__ __launch_bounds__(256) void split_h(
    const float* __restrict__ in, __half* __restrict__ oh, int n4)
{
    const int i = blockIdx.x * blockDim.x + threadIdx.x;
    if (i >= n4) return;
    const float4 v = ((const float4*)in)[i];
    __half h[4];
    h[0] = __float2half(v.x); h[1] = __float2half(v.y);
    h[2] = __float2half(v.z); h[3] = __float2half(v.w);
    *(uint2*)&oh[(size_t)i * 4] = *(uint2*)h;
}

// ---------------------------------------------------------------------------
// fp32 [R,C] -> transposed fp16 hi/lo [C,R]
// ---------------------------------------------------------------------------
__global__ __launch_bounds__(256) void tsplit_k(
    const float* __restrict__ in, int R, int C,
    __half* __restrict__ oh, size_t loOff)
{
    __shared__ float t[32][33];
    const int c0 = blockIdx.x * 32;
    const int rr0 = blockIdx.y * 32;
    const int tx = threadIdx.x;
    const int ty = threadIdx.y;
    #pragma unroll
    for (int i = 0; i < 4; i++)
        t[ty + 8 * i][tx] = in[(size_t)(rr0 + ty + 8 * i) * C + c0 + tx];
    __syncthreads();
    #pragma unroll
    for (int i = 0; i < 4; i++) {
        const float v = t[tx][ty + 8 * i];
        const __half hh = __float2half(v);
        const __half ll = __float2half(v - __half2float(hh));
        const size_t o = (size_t)(c0 + ty + 8 * i) * R + rr0 + tx;
        oh[o] = hh;
        oh[loOff + o] = ll;
    }
}

// ---------------------------------------------------------------------------
// out[c] = alpha * dot(bvec, Kmat[c,:])
// ---------------------------------------------------------------------------
__global__ __launch_bounds__(256) void bias_row_k(
    const float* __restrict__ bvec, const float* __restrict__ Kmat,
    int K, float alpha, float* __restrict__ outv)
{
    const int c = blockIdx.x;
    const int tid = threadIdx.x;
    float s = 0.0f;
    for (int k = tid; k < K; k += 256)
        s += bvec[k] * Kmat[(size_t)c * K + k];
    __shared__ float red[8];
    const int lane = tid & 31;
    const int warp = tid >> 5;
    #pragma unroll
    for (int o = 16; o > 0; o >>= 1)
        s += __shfl_xor_sync(0xffffffffu, s, o);
    if (lane == 0) red[warp] = s;
    __syncthreads();
    if (tid == 0) {
        float t = 0.0f;
        #pragma unroll
        for (int i = 0; i < 8; i++) t += red[i];
        outv[c] = t * alpha;
    }
}

// ---------------------------------------------------------------------------
// Masked softmax (LC=256 cols) -> fp16 hi
// ---------------------------------------------------------------------------
__global__ __launch_bounds__(256) void softmax_split_k(
    const float* __restrict__ att, const int* __restrict__ mask,
    __half* __restrict__ oh)
{
    const int row = blockIdx.x;
    const int c = threadIdx.x;
    const size_t idx = (size_t)row * LC_ + c;

    float v = att[idx];
    if (mask[row] != 0) v = -1e10f;

    __shared__ float red_max[8];
    __shared__ float red_sum[8];
    const int lane = c & 31;
    const int warp = c >> 5;

    float m = v;
    #pragma unroll
    for (int o = 16; o > 0; o >>= 1)
        m = fmaxf(m, __shfl_xor_sync(0xffffffffu, m, o));
    if (lane == 0) red_max[warp] = m;
    __syncthreads();
    float mmax = red_max[0];
    #pragma unroll
    for (int i = 1; i < 8; i++) mmax = fmaxf(mmax, red_max[i]);

    const float e = expf(v - mmax);

    float s = e;
    #pragma unroll
    for (int o = 16; o > 0; o >>= 1)
        s += __shfl_xor_sync(0xffffffffu, s, o);
    if (lane == 0) red_sum[warp] = s;
    __syncthreads();
    float ssum = red_sum[0];
    #pragma unroll
    for (int i = 1; i < 8; i++) ssum += red_sum[i];

    oh[idx] = __float2half(e / ssum);
}

// ---------------------------------------------------------------------------
// Copy drug_f into first half of drug output rows
// ---------------------------------------------------------------------------
__global__ __launch_bounds__(256) void copy_drug_kernel(
    const float* __restrict__ drug_f, float* __restrict__ out)
{
    const int idx = blockIdx.x * blockDim.x + threadIdx.x;
    if (idx >= MDR * (DE_ / 4)) return;
    const int m = idx / (DE_ / 4);
    const int n4 = idx % (DE_ / 4);
    const float4 v = ((const float4*)drug_f)[(size_t)m * (DE_ / 4) + n4];
    ((float4*)out)[(size_t)m * (2 * DE_ / 4) + n4] = v;
}

// ---------------------------------------------------------------------------
// dst[i] += src[i]   (float4 vectorized)
// ---------------------------------------------------------------------------
__global__ __launch_bounds__(256) void add_k(
    float* __restrict__ dst, const float* __restrict__ src, int n4)
{
    const int i = blockIdx.x * blockDim.x + threadIdx.x;
    if (i >= n4) return;
    float4 a = ((const float4*)src)[i];
    float4 d = ((float4*)dst)[i];
    d.x += a.x; d.y += a.y; d.z += a.z; d.w += a.w;
    ((float4*)dst)[i] = d;
}

// ---------------------------------------------------------------------------
// Launch — forked multi-stream graph
// ---------------------------------------------------------------------------
static inline void* sym(const void* s) {
    void* p = 0;
    cudaGetSymbolAddress(&p, s);
    return p;
}

extern "C" void kernel_launch(void* const* d_in, const int* in_sizes, int n_in,
                              void* d_out, int out_size)
{
    const float* pr_f    = (const float*)d_in[0];
    const float* drug_f  = (const float*)d_in[1];
    const float* pr_conf = (const float*)d_in[2];
    const float* dr_conf = (const float*)d_in[3];
    const float* Wq  = (const float*)d_in[4];
    const float* bq  = (const float*)d_in[5];
    const float* Wk  = (const float*)d_in[6];
    const float* bk  = (const float*)d_in[7];
    const float* Wq2 = (const float*)d_in[8];
    const float* bq2 = (const float*)d_in[9];
    const float* Wk2 = (const float*)d_in[10];
    const float* bk2 = (const float*)d_in[11];
    const float* Wpr = (const float*)d_in[12];
    const float* bpr = (const float*)d_in[13];
    const int* pmask = (const int*)d_in[14];
    const int* dmask = (const int*)d_in[15];

    float* out    = (float*)d_out;
    float* pr_out = out;                                  // [16384, 512]
    float* dr_out = out + (size_t)MPR * DE_;              // [4096, 1024]

    __half* prf    = (__half*)sym(g_prf);
    __half* drugf  = (__half*)sym(g_drugf);
    __half* prconf = (__half*)sym(g_prconf);
    __half* drconf = (__half*)sym(g_drconf);
    __half* Wqhl   = (__half*)sym(g_Wqhl);
    __half* WkT    = (__half*)sym(g_WkT);
    __half* Wq2hl  = (__half*)sym(g_Wq2hl);
    __half* Wk2T   = (__half*)sym(g_Wk2T);
    __half* WprTt  = (__half*)sym(g_WprTt);
    __half* WprTb  = (__half*)sym(g_WprTb);
    float*  Kpr    = (float*)sym(g_Kpr);
    __half* Kprhl  = (__half*)sym(g_Kprhl);
    __half* P1Thl  = (__half*)sym(g_P1Thl);
    __half* P2Thl  = (__half*)sym(g_P2Thl);
    float*  att    = (float*)sym(g_att);
    __half* atthl  = (__half*)sym(g_atthl);
    float*  bqrow  = (float*)sym(g_bqrow);
    float*  tmpO   = (float*)sym(g_tmpO);
    float*  Kdr    = (float*)sym(g_Kdr);
    __half* Kdrhl  = (__half*)sym(g_Kdrhl);
    __half* KdrT   = (__half*)sym(g_KdrT);
    __half* P1dThl = (__half*)sym(g_P1dThl);
    float*  attdr  = (float*)sym(g_attdr);
    __half* attdrhl= (__half*)sym(g_attdrhl);
    float*  bq2row = (float*)sym(g_bq2row);

    const float pr_alpha = 1.0f / 16.0f;
    const float dr_alpha = 1.0f / sqrtf((float)DE_);

    cudaStream_t s1, s2;
    cudaStreamCreateWithFlags(&s1, cudaStreamNonBlocking);
    cudaStreamCreateWithFlags(&s2, cudaStreamNonBlocking);
    cudaEvent_t evStart, evA, evQ, evJ1, evJ2, evK, evWq, evWb, evP2;
    cudaEventCreateWithFlags(&evStart, cudaEventDisableTiming);
    cudaEventCreateWithFlags(&evA, cudaEventDisableTiming);
    cudaEventCreateWithFlags(&evQ, cudaEventDisableTiming);
    cudaEventCreateWithFlags(&evJ1, cudaEventDisableTiming);
    cudaEventCreateWithFlags(&evJ2, cudaEventDisableTiming);
    cudaEventCreateWithFlags(&evK, cudaEventDisableTiming);
    cudaEventCreateWithFlags(&evWq, cudaEventDisableTiming);
    cudaEventCreateWithFlags(&evWb, cudaEventDisableTiming);
    cudaEventCreateWithFlags(&evP2, cudaEventDisableTiming);

    cudaEventRecord(evStart, 0);
    cudaStreamWaitEvent(s1, evStart, 0);
    cudaStreamWaitEvent(s2, evStart, 0);

    // ======== stream s1: pr_f hi-split, Wq/WprTb prep, prout1 ========
    {
        const int n4 = MPR * DP_ / 4;
        split_h<<<(n4 + 255) / 256, 256, 0, s1>>>(pr_f, prf, n4);
        cudaEventRecord(evA, s1);     // prf ready
        {
            const int w4 = DP_ * DP_ / 4;
            split_k<<<(w4 + 255) / 256, 256, 0, s1>>>(Wq, Wqhl, (size_t)DP_ * DP_, w4);
        }
        cudaEventRecord(evWq, s1);    // Wqhl ready (for P1T on stream 0)
        tsplit_k<<<dim3(DE_ / 32, DP_ / 32), dim3(32, 8), 0, s1>>>(
            Wpr + (size_t)DP_ * DE_, DP_, DE_, WprTb, (size_t)DE_ * DP_);
        cudaEventRecord(evWb, s1);    // WprTb ready (for P2T on s2)
        tsplit_k<<<dim3(DE_ / 32, DP_ / 32), dim3(32, 8), 0, s1>>>(
            Wpr, DP_, DE_, WprTt, (size_t)DE_ * DP_);
        // prout1 = pr_f @ WprTop + bpr   (1-combo hi*hi)
        gemm_mma<<<dim3(DE_ / 128, MPR / 128), 256, 0, s1>>>(
            prf, 0, WprTt, (size_t)DE_ * DP_, DP_, 1,
            pr_out, 0, DE_, (__half*)0, 0, 0, bpr, 1.0f);
        cudaEventRecord(evQ, s1);     // pr_out base ready
        cudaEventRecord(evJ1, s1);
    }

    // ======== stream s2: copy, entire drug path, then P2T ========
    {
        copy_drug_kernel<<<(MDR * (DE_ / 4) + 255) / 256, 256, 0, s2>>>(drug_f, dr_out);
        int n4 = MDR * DE_ / 4;
        split_h<<<(n4 + 255) / 256, 256, 0, s2>>>(drug_f, drugf, n4);
        n4 = LC_ * DE_ / 4;
        split_k<<<(n4 + 255) / 256, 256, 0, s2>>>(dr_conf, drconf, (size_t)LC_ * DE_, n4);
        n4 = DE_ * DE_ / 4;
        split_k<<<(n4 + 255) / 256, 256, 0, s2>>>(Wq2, Wq2hl, (size_t)DE_ * DE_, n4);
        tsplit_k<<<dim3(DE_ / 32, DE_ / 32), dim3(32, 8), 0, s2>>>(
            Wk2, DE_, DE_, Wk2T, (size_t)DE_ * DE_);
        // Kdr = dr_conf @ Wk2 + bk2 (2-combo; f32 + hi/lo out)
        gemm_mma<<<dim3(DE_ / 128, LC_ / 128), 256, 0, s2>>>(
            drconf, (size_t)LC_ * DE_, Wk2T, (size_t)DE_ * DE_, DE_, 2,
            Kdr, 0, DE_, Kdrhl, (size_t)LC_ * DE_, DE_, bk2, 1.0f);
        tsplit_k<<<dim3(DE_ / 32, LC_ / 32), dim3(32, 8), 0, s2>>>(
            Kdr, LC_, DE_, KdrT, (size_t)DE_ * LC_);
        // P1dT = Kdr @ Wq2^T (2-combo; hi/lo only — consumer reads hi only)
        gemm_mma<<<dim3(DE_ / 128, LC_ / 128), 256, 0, s2>>>(
            Kdrhl, (size_t)LC_ * DE_, Wq2hl, (size_t)DE_ * DE_, DE_, 2,
            (float*)0, 0, 0, P1dThl, (size_t)LC_ * DE_, DE_, (const float*)0, 1.0f);
        bias_row_k<<<LC_, 256, 0, s2>>>(bq2, Kdr, DE_, dr_alpha, bq2row);
        // att_dr = drug_f @ P1dT^T * dr_alpha + bq2row   (1-combo)
        gemm_mma<<<dim3(LC_ / 128, MDR / 128), 256, 0, s2>>>(
            drugf, 0, P1dThl, (size_t)LC_ * DE_, DE_, 1,
            attdr, 0, LC_, (__half*)0, 0, 0, bq2row, dr_alpha);
        softmax_split_k<<<MDR, 256, 0, s2>>>(attdr, dmask, attdrhl);
        // dr_out[:, 512:] = S_dr @ Kdr   (1-combo)
        gemm_mma<<<dim3(DE_ / 128, MDR / 128), 256, 0, s2>>>(
            attdrhl, 0, KdrT, (size_t)DE_ * LC_, LC_, 1,
            dr_out + DE_, 0, 2 * DE_, (__half*)0, 0, 0, (const float*)0, 1.0f);
        cudaEventRecord(evJ2, s2);
        // P2T = WprBot contracted with Kpr (2-combo; off critical path)
        cudaStreamWaitEvent(s2, evK, 0);
        cudaStreamWaitEvent(s2, evWb, 0);
        gemm_mma<<<dim3(LC_ / 128, DE_ / 128), 256, 0, s2>>>(
            WprTb, (size_t)DE_ * DP_, Kprhl, (size_t)LC_ * DP_, DP_, 2,
            (float*)0, 0, 0, P2Thl, (size_t)DE_ * LC_, LC_, (const float*)0, 1.0f);
        cudaEventRecord(evP2, s2);
    }

    // ======== stream 0: protein attention chain ========
    {
        int n4 = LC_ * DP_ / 4;
        split_k<<<(n4 + 255) / 256, 256>>>(pr_conf, prconf, (size_t)LC_ * DP_, n4);
        tsplit_k<<<dim3(DP_ / 32, DP_ / 32), dim3(32, 8)>>>(
            Wk, DP_, DP_, WkT, (size_t)DP_ * DP_);
        // Kpr = pr_conf @ Wk + bk (2-combo; f32 + hi/lo)
        gemm_mma<<<dim3(DP_ / 128, LC_ / 128), 256>>>(
            prconf, (size_t)LC_ * DP_, WkT, (size_t)DP_ * DP_, DP_, 2,
            Kpr, 0, DP_, Kprhl, (size_t)LC_ * DP_, DP_, bk, 1.0f);
        cudaEventRecord(evK, 0);      // Kprhl ready (for P2T on s2)
        bias_row_k<<<LC_, 256>>>(bq, Kpr, DP_, pr_alpha, bqrow);
        // P1T = Kpr @ Wq^T (2-combo; consumer att reads hi only)
        cudaStreamWaitEvent(0, evWq, 0);
        gemm_mma<<<dim3(DP_ / 128, LC_ / 128), 256>>>(
            Kprhl, (size_t)LC_ * DP_, Wqhl, (size_t)DP_ * DP_, DP_, 2,
            (float*)0, 0, 0, P1Thl, (size_t)LC_ * DP_, DP_, (const float*)0, 1.0f);
        // att = pr_f @ P1T^T / 16 + bqrow  (1-combo; needs prf from s1)
        cudaStreamWaitEvent(0, evA, 0);
        gemm_mma<<<dim3(LC_ / 128, MPR / 128), 256>>>(
            prf, 0, P1Thl, (size_t)LC_ * DP_, DP_, 1,
            att, 0, LC_, (__half*)0, 0, 0, bqrow, pr_alpha);
        softmax_split_k<<<MPR, 256>>>(att, pmask, atthl);
        // tmpO = S @ P2T^T  (1-combo; independent of prout1 now)
        cudaStreamWaitEvent(0, evP2, 0);
        gemm_mma<<<dim3(DE_ / 128, MPR / 128), 256>>>(
            atthl, 0, P2Thl, (size_t)DE_ * LC_, LC_, 1,
            tmpO, 0, DE_, (__half*)0, 0, 0, (const float*)0, 1.0f);
        // pr_out += tmpO  (needs prout1)
        cudaStreamWaitEvent(0, evQ, 0);
        {
            const int a4 = MPR * DE_ / 4;
            add_k<<<(a4 + 255) / 256, 256>>>(pr_out, tmpO, a4);
        }
    }

    cudaStreamWaitEvent(0, evJ1, 0);
    cudaStreamWaitEvent(0, evJ2, 0);

    cudaEventDestroy(evStart);
    cudaEventDestroy(evA);
    cudaEventDestroy(evQ);
    cudaEventDestroy(evJ1);
    cudaEventDestroy(evJ2);
    cudaEventDestroy(evK);
    cudaEventDestroy(evWq);
    cudaEventDestroy(evWb);
    cudaEventDestroy(evP2);
    cudaStreamDestroy(s1);
    cudaStreamDestroy(s2);
}

// round 17
// speedup vs baseline: 2.8339x; 1.0217x over previous
#include <cuda_runtime.h>
#include <cuda_fp16.h>
#include <cstdint>
#include <math.h>

// ---------------------------------------------------------------------------
// Problem constants
// ---------------------------------------------------------------------------
#define B_   16
#define LP_  1024
#define LD_  256
#define DP_  1280
#define DE_  512
#define LC_  256

#define MPR  (B_ * LP_)      // 16384
#define MDR  (B_ * LD_)      // 4096

// ---------------------------------------------------------------------------
// Helpers
// ---------------------------------------------------------------------------
__device__ __forceinline__ uint32_t smem_u32(const void* p) {
    uint32_t a;
    asm("{ .reg .u64 t; cvta.to.shared.u64 t, %1; cvt.u32.u64 %0, t; }"
        : "=r"(a) : "l"(p));
    return a;
}

__device__ __forceinline__ void cpa16(uint32_t saddr, const void* g) {
    asm volatile("cp.async.cg.shared.global [%0], [%1], 16;"
                 :: "r"(saddr), "l"(g) : "memory");
}
#define CP_COMMIT() asm volatile("cp.async.commit_group;" ::: "memory")
#define CP_WAIT0()  asm volatile("cp.async.wait_group 0;" ::: "memory")
#define CP_WAIT1()  asm volatile("cp.async.wait_group 1;" ::: "memory")

#define LDSM4(r, addr) \
    asm volatile("ldmatrix.sync.aligned.m8n8.x4.shared.b16 {%0,%1,%2,%3}, [%4];" \
        : "=r"((r)[0]), "=r"((r)[1]), "=r"((r)[2]), "=r"((r)[3]) : "r"(addr))

#define MMA16816(d, a, b) \
    asm volatile("mma.sync.aligned.m16n8k16.row.col.f32.f16.f16.f32 " \
        "{%0,%1,%2,%3}, {%4,%5,%6,%7}, {%8,%9}, {%0,%1,%2,%3};" \
        : "+f"((d)[0]), "+f"((d)[1]), "+f"((d)[2]), "+f"((d)[3]) \
        : "r"((a)[0]), "r"((a)[1]), "r"((a)[2]), "r"((a)[3]), \
          "r"((b)[0]), "r"((b)[1]))

// ---------------------------------------------------------------------------
// Scratch (fp16; hl buffers: hi at [0,sz), lo at [sz,2sz)); 16B aligned
// ---------------------------------------------------------------------------
__device__ __align__(16) __half g_prf   [(size_t)MPR * DP_];      // hi only
__device__ __align__(16) __half g_drugf [(size_t)MDR * DE_];      // hi only
__device__ __align__(16) __half g_prconf[2ull * LC_ * DP_];
__device__ __align__(16) __half g_drconf[(size_t)LC_ * DE_];      // hi only
__device__ __align__(16) __half g_Wqhl  [(size_t)DP_ * DP_];      // hi only
__device__ __align__(16) __half g_WkT   [2ull * DP_ * DP_];
__device__ __align__(16) __half g_Wq2hl [(size_t)DE_ * DE_];      // hi only
__device__ __align__(16) __half g_Wk2T  [2ull * DE_ * DE_];
__device__ __align__(16) __half g_WprTt [2ull * DE_ * DP_];
__device__ __align__(16) __half g_WprTb [2ull * DE_ * DP_];

__device__ __align__(16) float  g_Kpr   [(size_t)LC_ * DP_];
__device__ __align__(16) __half g_Kprhl [2ull * LC_ * DP_];
__device__ __align__(16) __half g_P1Thl [2ull * LC_ * DP_];
__device__ __align__(16) __half g_P2Thl [2ull * DE_ * LC_];
__device__ __align__(16) float  g_att   [(size_t)MPR * LC_];
__device__ __align__(16) __half g_atthl [(size_t)MPR * LC_];      // hi only
__device__ __align__(16) float  g_bqrow [LC_];
__device__ __align__(16) float  g_tmpO  [(size_t)MPR * DE_];      // S@P2T partial

__device__ __align__(16) float  g_Kdr   [(size_t)LC_ * DE_];
__device__ __align__(16) __half g_Kdrhl [2ull * LC_ * DE_];
__device__ __align__(16) __half g_KdrT  [2ull * DE_ * LC_];
__device__ __align__(16) __half g_P1dThl[2ull * LC_ * DE_];
__device__ __align__(16) float  g_attdr [(size_t)MDR * LC_];
__device__ __align__(16) __half g_attdrhl[(size_t)MDR * LC_];     // hi only
__device__ __align__(16) float  g_bq2row[LC_];

// ---------------------------------------------------------------------------
// mma.sync fp16 GEMM: C = alpha * A*B^T (+bias), hi/lo split accumulation.
// nC=3: (Ah,Bh),(Ah,Bl),(Al,Bh)   nC=2: (Ah,Bh),(Ah,Bl)   nC=1: (Ah,Bh)
// A:[M,K], B:[N,K] row-major fp16. Tile 128x128, K-stage 32, double-buffered.
// (R7 core — proven fastest config; do not touch.)
// ---------------------------------------------------------------------------
#define STG 10240
#define ROWB 80

__global__ __launch_bounds__(256) void gemm_mma(
    const __half* __restrict__ A, size_t aLo,
    const __half* __restrict__ Bm, size_t bLo,
    int K, int nC,
    float* __restrict__ outF, int accumF, int ldcF,
    __half* __restrict__ outH, size_t outLoH, int ldcH,
    const float* __restrict__ bias, float alpha)
{
    __shared__ __align__(16) char smem[4 * STG];
    const uint32_t sA = smem_u32(smem);
    const uint32_t sB = sA + 2 * STG;

    const int tid = threadIdx.x;
    const int lane = tid & 31;
    const int warp = tid >> 5;
    const int m0 = blockIdx.y * 128;
    const int n0 = blockIdx.x * 128;
    const int wm = (warp & 1) * 64;
    const int wn = (warp >> 1) * 32;

    const __half* Ap[3] = {A, A, A + aLo};
    const __half* Bp[3] = {Bm, Bm + bLo, Bm};

    const int Ks = K >> 5;
    const int total = nC * Ks;

    const int lr0 = tid >> 2;
    const int lc0 = (tid & 3) * 16;

    const int arow = lane & 15;
    const int acol = (lane >> 4) * 16;
    uint32_t aBase[4];
    #pragma unroll
    for (int i = 0; i < 4; i++)
        aBase[i] = sA + (wm + 16 * i + arow) * ROWB + acol;
    const int brow = (lane & 7) + ((lane >> 4) & 1) * 8;
    const int bcol = ((lane >> 3) & 1) * 16;
    uint32_t bBase[2];
    #pragma unroll
    for (int j = 0; j < 2; j++)
        bBase[j] = sB + (wn + 16 * j + brow) * ROWB + bcol;

    float acc[4][4][4];
    #pragma unroll
    for (int i = 0; i < 4; i++)
        #pragma unroll
        for (int j = 0; j < 4; j++)
            #pragma unroll
            for (int e = 0; e < 4; e++) acc[i][j][e] = 0.0f;

    auto load_stage = [&](int s) {
        const int p = s / Ks;
        const int t = s - p * Ks;
        const int buf = s & 1;
        const char* Ag = (const char*)Ap[p];
        const char* Bg = (const char*)Bp[p];
        const size_t kb = (size_t)t * 64;
        #pragma unroll
        for (int h = 0; h < 2; h++) {
            const int row = lr0 + h * 64;
            const uint32_t sa = buf * STG + row * ROWB + lc0;
            cpa16(sA + sa, Ag + ((size_t)(m0 + row) * K) * 2 + kb + lc0);
            cpa16(sB + sa, Bg + ((size_t)(n0 + row) * K) * 2 + kb + lc0);
        }
        CP_COMMIT();
    };

    load_stage(0);
    load_stage(1);

    for (int s = 0; s < total; s++) {
        if (s + 1 < total) { CP_WAIT1(); } else { CP_WAIT0(); }
        __syncthreads();

        const int buf = s & 1;
        const uint32_t off = buf * STG;
        #pragma unroll
        for (int kstep = 0; kstep < 2; kstep++) {
            uint32_t aF[4][4], bF[2][4];
            #pragma unroll
            for (int i = 0; i < 4; i++)
                LDSM4(aF[i], aBase[i] + off + kstep * 32);
            #pragma unroll
            for (int j = 0; j < 2; j++)
                LDSM4(bF[j], bBase[j] + off + kstep * 32);
            #pragma unroll
            for (int i = 0; i < 4; i++)
                #pragma unroll
                for (int j = 0; j < 4; j++) {
                    uint32_t bb[2] = {bF[j >> 1][(j & 1) * 2],
                                      bF[j >> 1][(j & 1) * 2 + 1]};
                    MMA16816(acc[i][j], aF[i], bb);
                }
        }
        __syncthreads();
        if (s + 2 < total) load_stage(s + 2);
    }

    const int mrow = m0 + wm + (lane >> 2);
    const int ncb  = n0 + wn + 2 * (lane & 3);

    #pragma unroll
    for (int j = 0; j < 4; j++) {
        const int n = ncb + 8 * j;
        float badd0 = 0.0f, badd1 = 0.0f;
        if (bias) { badd0 = bias[n]; badd1 = bias[n + 1]; }
        #pragma unroll
        for (int i = 0; i < 4; i++) {
            #pragma unroll
            for (int half_ = 0; half_ < 2; half_++) {
                const int m = mrow + 16 * i + 8 * half_;
                float v0 = acc[i][j][2 * half_ + 0] * alpha + badd0;
                float v1 = acc[i][j][2 * half_ + 1] * alpha + badd1;
                if (outH) {
                    const size_t base = (size_t)m * ldcH + n;
                    const __half h0 = __float2half(v0);
                    const __half h1 = __float2half(v1);
                    const __half l0 = __float2half(v0 - __half2float(h0));
                    const __half l1 = __float2half(v1 - __half2float(h1));
                    *(__half2*)&outH[base] = __halves2half2(h0, h1);
                    *(__half2*)&outH[base + outLoH] = __halves2half2(l0, l1);
                }
                if (outF) {
                    const size_t base = (size_t)m * ldcF + n;
                    if (accumF) {
                        float2 o = *(float2*)&outF[base];
                        v0 += o.x; v1 += o.y;
                    }
                    float2 w; w.x = v0; w.y = v1;
                    *(float2*)&outF[base] = w;
                }
            }
        }
    }
}

// ---------------------------------------------------------------------------
// fp32 -> fp16 hi/lo split
// ---------------------------------------------------------------------------
__global__ __launch_bounds__(256) void split_k(
    const float* __restrict__ in, __half* __restrict__ oh,
    size_t loOff, int n4)
{
    const int i = blockIdx.x * blockDim.x + threadIdx.x;
    if (i >= n4) return;
    const float4 v = ((const float4*)in)[i];
    const float vv[4] = {v.x, v.y, v.z, v.w};
    __half h[4], l[4];
    #pragma unroll
    for (int j = 0; j < 4; j++) {
        h[j] = __float2half(vv[j]);
        l[j] = __float2half(vv[j] - __half2float(h[j]));
    }
    *(uint2*)&oh[(size_t)i * 4]         = *(uint2*)h;
    *(uint2*)&oh[loOff + (size_t)i * 4] = *(uint2*)l;
}

// fp32 -> fp16 hi only
__global__ __launch_bounds__(256) void split_h(
    const float* __restrict__ in, __half* __restrict__ oh, int n4)
{
    const int i = blockIdx.x * blockDim.x + threadIdx.x;
    if (i >= n4) return;
    const float4 v = ((const float4*)in)[i];
    __half h[4];
    h[0] = __float2half(v.x); h[1] = __float2half(v.y);
    h[2] = __float2half(v.z); h[3] = __float2half(v.w);
    *(uint2*)&oh[(size_t)i * 4] = *(uint2*)h;
}

// ---------------------------------------------------------------------------
// fp32 [R,C] -> transposed fp16 hi/lo [C,R]
// ---------------------------------------------------------------------------
__global__ __launch_bounds__(256) void tsplit_k(
    const float* __restrict__ in, int R, int C,
    __half* __restrict__ oh, size_t loOff)
{
    __shared__ float t[32][33];
    const int c0 = blockIdx.x * 32;
    const int rr0 = blockIdx.y * 32;
    const int tx = threadIdx.x;
    const int ty = threadIdx.y;
    #pragma unroll
    for (int i = 0; i < 4; i++)
        t[ty + 8 * i][tx] = in[(size_t)(rr0 + ty + 8 * i) * C + c0 + tx];
    __syncthreads();
    #pragma unroll
    for (int i = 0; i < 4; i++) {
        const float v = t[tx][ty + 8 * i];
        const __half hh = __float2half(v);
        const __half ll = __float2half(v - __half2float(hh));
        const size_t o = (size_t)(c0 + ty + 8 * i) * R + rr0 + tx;
        oh[o] = hh;
        oh[loOff + o] = ll;
    }
}

// ---------------------------------------------------------------------------
// out[c] = alpha * dot(bvec, Kmat[c,:])
// ---------------------------------------------------------------------------
__global__ __launch_bounds__(256) void bias_row_k(
    const float* __restrict__ bvec, const float* __restrict__ Kmat,
    int K, float alpha, float* __restrict__ outv)
{
    const int c = blockIdx.x;
    const int tid = threadIdx.x;
    float s = 0.0f;
    for (int k = tid; k < K; k += 256)
        s += bvec[k] * Kmat[(size_t)c * K + k];
    __shared__ float red[8];
    const int lane = tid & 31;
    const int warp = tid >> 5;
    #pragma unroll
    for (int o = 16; o > 0; o >>= 1)
        s += __shfl_xor_sync(0xffffffffu, s, o);
    if (lane == 0) red[warp] = s;
    __syncthreads();
    if (tid == 0) {
        float t = 0.0f;
        #pragma unroll
        for (int i = 0; i < 8; i++) t += red[i];
        outv[c] = t * alpha;
    }
}

// ---------------------------------------------------------------------------
// Masked softmax (LC=256 cols) -> fp16 hi
// ---------------------------------------------------------------------------
__global__ __launch_bounds__(256) void softmax_split_k(
    const float* __restrict__ att, const int* __restrict__ mask,
    __half* __restrict__ oh)
{
    const int row = blockIdx.x;
    const int c = threadIdx.x;
    const size_t idx = (size_t)row * LC_ + c;

    float v = att[idx];
    if (mask[row] != 0) v = -1e10f;

    __shared__ float red_max[8];
    __shared__ float red_sum[8];
    const int lane = c & 31;
    const int warp = c >> 5;

    float m = v;
    #pragma unroll
    for (int o = 16; o > 0; o >>= 1)
        m = fmaxf(m, __shfl_xor_sync(0xffffffffu, m, o));
    if (lane == 0) red_max[warp] = m;
    __syncthreads();
    float mmax = red_max[0];
    #pragma unroll
    for (int i = 1; i < 8; i++) mmax = fmaxf(mmax, red_max[i]);

    const float e = expf(v - mmax);

    float s = e;
    #pragma unroll
    for (int o = 16; o > 0; o >>= 1)
        s += __shfl_xor_sync(0xffffffffu, s, o);
    if (lane == 0) red_sum[warp] = s;
    __syncthreads();
    float ssum = red_sum[0];
    #pragma unroll
    for (int i = 1; i < 8; i++) ssum += red_sum[i];

    oh[idx] = __float2half(e / ssum);
}

// ---------------------------------------------------------------------------
// Copy drug_f into first half of drug output rows
// ---------------------------------------------------------------------------
__global__ __launch_bounds__(256) void copy_drug_kernel(
    const float* __restrict__ drug_f, float* __restrict__ out)
{
    const int idx = blockIdx.x * blockDim.x + threadIdx.x;
    if (idx >= MDR * (DE_ / 4)) return;
    const int m = idx / (DE_ / 4);
    const int n4 = idx % (DE_ / 4);
    const float4 v = ((const float4*)drug_f)[(size_t)m * (DE_ / 4) + n4];
    ((float4*)out)[(size_t)m * (2 * DE_ / 4) + n4] = v;
}

// ---------------------------------------------------------------------------
// dst[i] += src[i]   (float4 vectorized)
// ---------------------------------------------------------------------------
__global__ __launch_bounds__(256) void add_k(
    float* __restrict__ dst, const float* __restrict__ src, int n4)
{
    const int i = blockIdx.x * blockDim.x + threadIdx.x;
    if (i >= n4) return;
    float4 a = ((const float4*)src)[i];
    float4 d = ((float4*)dst)[i];
    d.x += a.x; d.y += a.y; d.z += a.z; d.w += a.w;
    ((float4*)dst)[i] = d;
}

// ---------------------------------------------------------------------------
// Launch — forked multi-stream graph
// ---------------------------------------------------------------------------
static inline void* sym(const void* s) {
    void* p = 0;
    cudaGetSymbolAddress(&p, s);
    return p;
}

extern "C" void kernel_launch(void* const* d_in, const int* in_sizes, int n_in,
                              void* d_out, int out_size)
{
    const float* pr_f    = (const float*)d_in[0];
    const float* drug_f  = (const float*)d_in[1];
    const float* pr_conf = (const float*)d_in[2];
    const float* dr_conf = (const float*)d_in[3];
    const float* Wq  = (const float*)d_in[4];
    const float* bq  = (const float*)d_in[5];
    const float* Wk  = (const float*)d_in[6];
    const float* bk  = (const float*)d_in[7];
    const float* Wq2 = (const float*)d_in[8];
    const float* bq2 = (const float*)d_in[9];
    const float* Wk2 = (const float*)d_in[10];
    const float* bk2 = (const float*)d_in[11];
    const float* Wpr = (const float*)d_in[12];
    const float* bpr = (const float*)d_in[13];
    const int* pmask = (const int*)d_in[14];
    const int* dmask = (const int*)d_in[15];

    float* out    = (float*)d_out;
    float* pr_out = out;                                  // [16384, 512]
    float* dr_out = out + (size_t)MPR * DE_;              // [4096, 1024]

    __half* prf    = (__half*)sym(g_prf);
    __half* drugf  = (__half*)sym(g_drugf);
    __half* prconf = (__half*)sym(g_prconf);
    __half* drconf = (__half*)sym(g_drconf);
    __half* Wqhl   = (__half*)sym(g_Wqhl);
    __half* WkT    = (__half*)sym(g_WkT);
    __half* Wq2hl  = (__half*)sym(g_Wq2hl);
    __half* Wk2T   = (__half*)sym(g_Wk2T);
    __half* WprTt  = (__half*)sym(g_WprTt);
    __half* WprTb  = (__half*)sym(g_WprTb);
    float*  Kpr    = (float*)sym(g_Kpr);
    __half* Kprhl  = (__half*)sym(g_Kprhl);
    __half* P1Thl  = (__half*)sym(g_P1Thl);
    __half* P2Thl  = (__half*)sym(g_P2Thl);
    float*  att    = (float*)sym(g_att);
    __half* atthl  = (__half*)sym(g_atthl);
    float*  bqrow  = (float*)sym(g_bqrow);
    float*  tmpO   = (float*)sym(g_tmpO);
    float*  Kdr    = (float*)sym(g_Kdr);
    __half* Kdrhl  = (__half*)sym(g_Kdrhl);
    __half* KdrT   = (__half*)sym(g_KdrT);
    __half* P1dThl = (__half*)sym(g_P1dThl);
    float*  attdr  = (float*)sym(g_attdr);
    __half* attdrhl= (__half*)sym(g_attdrhl);
    float*  bq2row = (float*)sym(g_bq2row);

    const float pr_alpha = 1.0f / 16.0f;
    const float dr_alpha = 1.0f / sqrtf((float)DE_);

    cudaStream_t s1, s2;
    cudaStreamCreateWithFlags(&s1, cudaStreamNonBlocking);
    cudaStreamCreateWithFlags(&s2, cudaStreamNonBlocking);
    cudaEvent_t evStart, evA, evQ, evJ1, evJ2, evK, evP2;
    cudaEventCreateWithFlags(&evStart, cudaEventDisableTiming);
    cudaEventCreateWithFlags(&evA, cudaEventDisableTiming);
    cudaEventCreateWithFlags(&evQ, cudaEventDisableTiming);
    cudaEventCreateWithFlags(&evJ1, cudaEventDisableTiming);
    cudaEventCreateWithFlags(&evJ2, cudaEventDisableTiming);
    cudaEventCreateWithFlags(&evK, cudaEventDisableTiming);
    cudaEventCreateWithFlags(&evP2, cudaEventDisableTiming);

    cudaEventRecord(evStart, 0);
    cudaStreamWaitEvent(s1, evStart, 0);
    cudaStreamWaitEvent(s2, evStart, 0);

    // ======== stream s1: prf split -> WprTt -> prout1 (earliest start) ======
    {
        const int n4 = MPR * DP_ / 4;
        split_h<<<(n4 + 255) / 256, 256, 0, s1>>>(pr_f, prf, n4);
        cudaEventRecord(evA, s1);     // prf ready
        tsplit_k<<<dim3(DE_ / 32, DP_ / 32), dim3(32, 8), 0, s1>>>(
            Wpr, DP_, DE_, WprTt, (size_t)DE_ * DP_);
        // prout1 = pr_f @ WprTop + bpr   (1-combo hi*hi)
        gemm_mma<<<dim3(DE_ / 128, MPR / 128), 256, 0, s1>>>(
            prf, 0, WprTt, (size_t)DE_ * DP_, DP_, 1,
            pr_out, 0, DE_, (__half*)0, 0, 0, bpr, 1.0f);
        cudaEventRecord(evQ, s1);     // pr_out base ready
        cudaEventRecord(evJ1, s1);
    }

    // ======== stream s2: WprTb prep, copy, drug path, then P2T ========
    {
        tsplit_k<<<dim3(DE_ / 32, DP_ / 32), dim3(32, 8), 0, s2>>>(
            Wpr + (size_t)DP_ * DE_, DP_, DE_, WprTb, (size_t)DE_ * DP_);
        copy_drug_kernel<<<(MDR * (DE_ / 4) + 255) / 256, 256, 0, s2>>>(drug_f, dr_out);
        int n4 = MDR * DE_ / 4;
        split_h<<<(n4 + 255) / 256, 256, 0, s2>>>(drug_f, drugf, n4);
        n4 = LC_ * DE_ / 4;
        split_h<<<(n4 + 255) / 256, 256, 0, s2>>>(dr_conf, drconf, n4);
        n4 = DE_ * DE_ / 4;
        split_h<<<(n4 + 255) / 256, 256, 0, s2>>>(Wq2, Wq2hl, n4);
        tsplit_k<<<dim3(DE_ / 32, DE_ / 32), dim3(32, 8), 0, s2>>>(
            Wk2, DE_, DE_, Wk2T, (size_t)DE_ * DE_);
        // Kdr = dr_conf @ Wk2 + bk2 (1-combo; f32 + hi/lo out)
        gemm_mma<<<dim3(DE_ / 128, LC_ / 128), 256, 0, s2>>>(
            drconf, 0, Wk2T, (size_t)DE_ * DE_, DE_, 1,
            Kdr, 0, DE_, Kdrhl, (size_t)LC_ * DE_, DE_, bk2, 1.0f);
        tsplit_k<<<dim3(DE_ / 32, LC_ / 32), dim3(32, 8), 0, s2>>>(
            Kdr, LC_, DE_, KdrT, (size_t)DE_ * LC_);
        // P1dT = Kdr @ Wq2^T (1-combo; hi/lo only — consumer reads hi only)
        gemm_mma<<<dim3(DE_ / 128, LC_ / 128), 256, 0, s2>>>(
            Kdrhl, 0, Wq2hl, 0, DE_, 1,
            (float*)0, 0, 0, P1dThl, (size_t)LC_ * DE_, DE_, (const float*)0, 1.0f);
        bias_row_k<<<LC_, 256, 0, s2>>>(bq2, Kdr, DE_, dr_alpha, bq2row);
        // att_dr = drug_f @ P1dT^T * dr_alpha + bq2row   (1-combo)
        gemm_mma<<<dim3(LC_ / 128, MDR / 128), 256, 0, s2>>>(
            drugf, 0, P1dThl, 0, DE_, 1,
            attdr, 0, LC_, (__half*)0, 0, 0, bq2row, dr_alpha);
        softmax_split_k<<<MDR, 256, 0, s2>>>(attdr, dmask, attdrhl);
        // dr_out[:, 512:] = S_dr @ Kdr   (1-combo)
        gemm_mma<<<dim3(DE_ / 128, MDR / 128), 256, 0, s2>>>(
            attdrhl, 0, KdrT, 0, LC_, 1,
            dr_out + DE_, 0, 2 * DE_, (__half*)0, 0, 0, (const float*)0, 1.0f);
        cudaEventRecord(evJ2, s2);
        // P2T = WprBot contracted with Kpr (2-combo; off critical path)
        cudaStreamWaitEvent(s2, evK, 0);
        gemm_mma<<<dim3(LC_ / 128, DE_ / 128), 256, 0, s2>>>(
            WprTb, (size_t)DE_ * DP_, Kprhl, (size_t)LC_ * DP_, DP_, 2,
            (float*)0, 0, 0, P2Thl, (size_t)DE_ * LC_, LC_, (const float*)0, 1.0f);
        cudaEventRecord(evP2, s2);
    }

    // ======== stream 0: protein attention chain ========
    {
        {
            const int w4 = DP_ * DP_ / 4;
            split_h<<<(w4 + 255) / 256, 256>>>(Wq, Wqhl, w4);
        }
        int n4 = LC_ * DP_ / 4;
        split_k<<<(n4 + 255) / 256, 256>>>(pr_conf, prconf, (size_t)LC_ * DP_, n4);
        tsplit_k<<<dim3(DP_ / 32, DP_ / 32), dim3(32, 8)>>>(
            Wk, DP_, DP_, WkT, (size_t)DP_ * DP_);
        // Kpr = pr_conf @ Wk + bk (2-combo; f32 + hi/lo)
        gemm_mma<<<dim3(DP_ / 128, LC_ / 128), 256>>>(
            prconf, (size_t)LC_ * DP_, WkT, (size_t)DP_ * DP_, DP_, 2,
            Kpr, 0, DP_, Kprhl, (size_t)LC_ * DP_, DP_, bk, 1.0f);
        cudaEventRecord(evK, 0);      // Kprhl ready (for P2T on s2)
        bias_row_k<<<LC_, 256>>>(bq, Kpr, DP_, pr_alpha, bqrow);
        // P1T = Kpr @ Wq^T (1-combo; att reads hi only, logit path insensitive)
        gemm_mma<<<dim3(DP_ / 128, LC_ / 128), 256>>>(
            Kprhl, 0, Wqhl, 0, DP_, 1,
            (float*)0, 0, 0, P1Thl, (size_t)LC_ * DP_, DP_, (const float*)0, 1.0f);
        // att = pr_f @ P1T^T / 16 + bqrow  (1-combo; needs prf from s1)
        cudaStreamWaitEvent(0, evA, 0);
        gemm_mma<<<dim3(LC_ / 128, MPR / 128), 256>>>(
            prf, 0, P1Thl, 0, DP_, 1,
            att, 0, LC_, (__half*)0, 0, 0, bqrow, pr_alpha);
        softmax_split_k<<<MPR, 256>>>(att, pmask, atthl);
        // tmpO = S @ P2T^T  (1-combo; independent of prout1)
        cudaStreamWaitEvent(0, evP2, 0);
        gemm_mma<<<dim3(DE_ / 128, MPR / 128), 256>>>(
            atthl, 0, P2Thl, 0, LC_, 1,
            tmpO, 0, DE_, (__half*)0, 0, 0, (const float*)0, 1.0f);
        // pr_out += tmpO  (needs prout1)
        cudaStreamWaitEvent(0, evQ, 0);
        {
            const int a4 = MPR * DE_ / 4;
            add_k<<<(a4 + 255) / 256, 256>>>(pr_out, tmpO, a4);
        }
    }

    cudaStreamWaitEvent(0, evJ1, 0);
    cudaStreamWaitEvent(0, evJ2, 0);

    cudaEventDestroy(evStart);
    cudaEventDestroy(evA);
    cudaEventDestroy(evQ);
    cudaEventDestroy(evJ1);
    cudaEventDestroy(evJ2);
    cudaEventDestroy(evK);
    cudaEventDestroy(evP2);
    cudaStreamDestroy(s1);
    cudaStreamDestroy(s2);
}